// round 1
// baseline (speedup 1.0000x reference)
#include <cuda_runtime.h>
#include <cstddef>

// ---------------------------------------------------------------------------
// EncoderLayer: B=4, S=1024, D=1024, H=16, HD=64, DFF=4096, fp32
// Outputs: out2 [B,S,D] then attn_weights [B,H,S,S] (flattened, concatenated)
// NOTE: reference projects q,k,v ALL through Wq -> q==k==v, compute once.
// ---------------------------------------------------------------------------

#define B_  4
#define S_  1024
#define D_  1024
#define H_  16
#define HD_ 64
#define DFF_ 4096
#define ROWS_ (B_*S_)          // 4096
#define BH_ (B_*H_)            // 64

// Scratch (device globals; no allocation allowed)
__device__ float g_q[ROWS_ * D_];          // q==k==v projection   (16 MB)
__device__ float g_attn_out[ROWS_ * D_];   // attention output     (16 MB)
__device__ float g_proj[ROWS_ * D_];       // attn@Wo  /  ffn2 out (16 MB)
__device__ float g_out1[ROWS_ * D_];       // LN1 output           (16 MB)
__device__ float g_ff1[(size_t)ROWS_ * DFF_]; // relu(out1@W1+b1)  (64 MB)

// ---------------------------------------------------------------------------
// Generic NN SGEMM: C[M,N] = A[M,K] @ B[K,N] + bias, optional ReLU.
// BM=BN=128, BK=8, 256 threads, 8x8 per thread. M,N multiples of 128,
// K multiple of 8 (true for all call sites).
// ---------------------------------------------------------------------------
template<int RELU>
__global__ __launch_bounds__(256) void sgemm_nn(
    const float* __restrict__ A, int lda,
    const float* __restrict__ Bm, int ldb,
    float* __restrict__ C, int ldc,
    int K, const float* __restrict__ bias)
{
    __shared__ float As[8][128];
    __shared__ float Bs[8][128];
    const int tid = threadIdx.x;
    const int bm = blockIdx.y * 128;
    const int bn = blockIdx.x * 128;
    const int arow = tid >> 1;           // 0..127
    const int acol = (tid & 1) * 4;      // 0 or 4
    const int brow = tid >> 5;           // 0..7
    const int bcol = (tid & 31) * 4;     // 0..124
    const int tm = (tid >> 4) * 8;
    const int tn = (tid & 15) * 8;

    float acc[8][8] = {};
    const float* Ap = A + (size_t)(bm + arow) * lda + acol;
    const float* Bp = Bm + (size_t)brow * ldb + bn + bcol;

    for (int kk = 0; kk < K; kk += 8) {
        float4 a4 = *(const float4*)(Ap + kk);
        As[acol + 0][arow] = a4.x;
        As[acol + 1][arow] = a4.y;
        As[acol + 2][arow] = a4.z;
        As[acol + 3][arow] = a4.w;
        *(float4*)&Bs[brow][bcol] = *(const float4*)(Bp + (size_t)kk * ldb);
        __syncthreads();
        #pragma unroll
        for (int k = 0; k < 8; k++) {
            float ra[8], rb[8];
            #pragma unroll
            for (int i = 0; i < 8; i++) ra[i] = As[k][tm + i];
            #pragma unroll
            for (int j = 0; j < 8; j++) rb[j] = Bs[k][tn + j];
            #pragma unroll
            for (int i = 0; i < 8; i++)
                #pragma unroll
                for (int j = 0; j < 8; j++)
                    acc[i][j] = fmaf(ra[i], rb[j], acc[i][j]);
        }
        __syncthreads();
    }

    #pragma unroll
    for (int i = 0; i < 8; i++) {
        #pragma unroll
        for (int j = 0; j < 8; j++) {
            float v = acc[i][j] + bias[bn + tn + j];
            if (RELU) v = fmaxf(v, 0.0f);
            C[(size_t)(bm + tm + i) * ldc + bn + tn + j] = v;
        }
    }
}

// ---------------------------------------------------------------------------
// Scores: per head z=b*H+h, C = (Qh @ Qh^T) * (1/8). Qh is the strided head
// slice of g_q: rows S_, cols HD_=64, row stride D_. Output ld = S_.
// ---------------------------------------------------------------------------
__global__ __launch_bounds__(256) void sgemm_scores(
    const float* __restrict__ qbuf, float* __restrict__ attn)
{
    const int z = blockIdx.z;
    const int b = z >> 4, h = z & 15;
    const float* A = qbuf + (size_t)b * S_ * D_ + h * HD_;
    float* C = attn + (size_t)z * S_ * S_;

    __shared__ float As[8][128];
    __shared__ float Bs[8][128];
    const int tid = threadIdx.x;
    const int bm = blockIdx.y * 128;
    const int bn = blockIdx.x * 128;
    const int arow = tid >> 1;
    const int acol = (tid & 1) * 4;
    const int tm = (tid >> 4) * 8;
    const int tn = (tid & 15) * 8;

    float acc[8][8] = {};
    for (int kk = 0; kk < HD_; kk += 8) {
        float4 a4 = *(const float4*)(A + (size_t)(bm + arow) * D_ + kk + acol);
        As[acol + 0][arow] = a4.x;
        As[acol + 1][arow] = a4.y;
        As[acol + 2][arow] = a4.z;
        As[acol + 3][arow] = a4.w;
        float4 b4 = *(const float4*)(A + (size_t)(bn + arow) * D_ + kk + acol);
        Bs[acol + 0][arow] = b4.x;
        Bs[acol + 1][arow] = b4.y;
        Bs[acol + 2][arow] = b4.z;
        Bs[acol + 3][arow] = b4.w;
        __syncthreads();
        #pragma unroll
        for (int k = 0; k < 8; k++) {
            float ra[8], rb[8];
            #pragma unroll
            for (int i = 0; i < 8; i++) ra[i] = As[k][tm + i];
            #pragma unroll
            for (int j = 0; j < 8; j++) rb[j] = Bs[k][tn + j];
            #pragma unroll
            for (int i = 0; i < 8; i++)
                #pragma unroll
                for (int j = 0; j < 8; j++)
                    acc[i][j] = fmaf(ra[i], rb[j], acc[i][j]);
        }
        __syncthreads();
    }

    #pragma unroll
    for (int i = 0; i < 8; i++)
        #pragma unroll
        for (int j = 0; j < 8; j++)
            C[(size_t)(bm + tm + i) * S_ + bn + tn + j] = acc[i][j] * 0.125f;
}

// ---------------------------------------------------------------------------
// Softmax with mask, row-wise in place over attn rows of length S_.
// grid = (S_, B*H). mask row is per (b, qrow), shared across heads.
// ---------------------------------------------------------------------------
__global__ __launch_bounds__(256) void softmax_kernel(
    float* __restrict__ attn, const int* __restrict__ mask)
{
    const int q = blockIdx.x;
    const int z = blockIdx.y;
    const int b = z >> 4;
    float* row = attn + (size_t)z * S_ * S_ + (size_t)q * S_;
    const int* mrow = mask + (size_t)b * S_ * S_ + (size_t)q * S_;
    const int tid = threadIdx.x;

    float4 v = ((const float4*)row)[tid];
    int4 m = ((const int4*)mrow)[tid];
    if (m.x == 0) v.x = -1e9f;
    if (m.y == 0) v.y = -1e9f;
    if (m.z == 0) v.z = -1e9f;
    if (m.w == 0) v.w = -1e9f;

    __shared__ float sred[8];
    const int w = tid >> 5, l = tid & 31;

    // max reduce
    float mx = fmaxf(fmaxf(v.x, v.y), fmaxf(v.z, v.w));
    #pragma unroll
    for (int o = 16; o; o >>= 1) mx = fmaxf(mx, __shfl_xor_sync(~0u, mx, o));
    if (l == 0) sred[w] = mx;
    __syncthreads();
    mx = fmaxf(fmaxf(fmaxf(sred[0], sred[1]), fmaxf(sred[2], sred[3])),
               fmaxf(fmaxf(sred[4], sred[5]), fmaxf(sred[6], sred[7])));
    __syncthreads();

    v.x = __expf(v.x - mx);
    v.y = __expf(v.y - mx);
    v.z = __expf(v.z - mx);
    v.w = __expf(v.w - mx);

    float s = v.x + v.y + v.z + v.w;
    #pragma unroll
    for (int o = 16; o; o >>= 1) s += __shfl_xor_sync(~0u, s, o);
    if (l == 0) sred[w] = s;
    __syncthreads();
    s = (sred[0] + sred[1]) + (sred[2] + sred[3]) +
        (sred[4] + sred[5]) + (sred[6] + sred[7]);

    const float inv = 1.0f / s;
    v.x *= inv; v.y *= inv; v.z *= inv; v.w *= inv;
    ((float4*)row)[tid] = v;
}

// ---------------------------------------------------------------------------
// PV: per head z, C[S_,HD_] = P[S_,S_] @ V[S_,HD_]. V is the strided head
// slice of g_q. BM=128, BN=64, BK=8, 256 threads, 8x4 per thread.
// ---------------------------------------------------------------------------
__global__ __launch_bounds__(256) void sgemm_pv(
    const float* __restrict__ attn, const float* __restrict__ qbuf,
    float* __restrict__ out)
{
    const int z = blockIdx.z;
    const int b = z >> 4, h = z & 15;
    const float* A = attn + (size_t)z * S_ * S_;               // P, lda = S_
    const float* Bv = qbuf + (size_t)b * S_ * D_ + h * HD_;    // V, ldb = D_
    float* C = out + (size_t)b * S_ * D_ + h * HD_;            // ldc = D_

    __shared__ float As[8][128];
    __shared__ float Bs[8][64];
    const int tid = threadIdx.x;
    const int bm = blockIdx.y * 128;
    const int arow = tid >> 1;
    const int acol = (tid & 1) * 4;
    const int bk = tid >> 5;             // 0..7
    const int bn2 = (tid & 31) * 2;      // 0..62
    const int tm = (tid >> 4) * 8;
    const int tn = (tid & 15) * 4;

    float acc[8][4] = {};
    for (int kk = 0; kk < S_; kk += 8) {
        float4 a4 = *(const float4*)(A + (size_t)(bm + arow) * S_ + kk + acol);
        As[acol + 0][arow] = a4.x;
        As[acol + 1][arow] = a4.y;
        As[acol + 2][arow] = a4.z;
        As[acol + 3][arow] = a4.w;
        float2 b2 = *(const float2*)(Bv + (size_t)(kk + bk) * D_ + bn2);
        Bs[bk][bn2] = b2.x;
        Bs[bk][bn2 + 1] = b2.y;
        __syncthreads();
        #pragma unroll
        for (int k = 0; k < 8; k++) {
            float ra[8], rb[4];
            #pragma unroll
            for (int i = 0; i < 8; i++) ra[i] = As[k][tm + i];
            #pragma unroll
            for (int j = 0; j < 4; j++) rb[j] = Bs[k][tn + j];
            #pragma unroll
            for (int i = 0; i < 8; i++)
                #pragma unroll
                for (int j = 0; j < 4; j++)
                    acc[i][j] = fmaf(ra[i], rb[j], acc[i][j]);
        }
        __syncthreads();
    }

    #pragma unroll
    for (int i = 0; i < 8; i++)
        #pragma unroll
        for (int j = 0; j < 4; j++)
            C[(size_t)(bm + tm + i) * D_ + tn + j] = acc[i][j];
}

// ---------------------------------------------------------------------------
// Fused residual add + LayerNorm. One block per row, D_=1024 = 256 thr * 4.
// out = g * ((a+b) - mean) * rsqrt(var + 1e-12) + beta
// ---------------------------------------------------------------------------
__global__ __launch_bounds__(256) void add_ln_kernel(
    const float* __restrict__ a, const float* __restrict__ bres,
    const float* __restrict__ g, const float* __restrict__ beta,
    float* __restrict__ out)
{
    const size_t r = blockIdx.x;
    const int tid = threadIdx.x;
    float4 va = ((const float4*)(a + r * D_))[tid];
    float4 vb = ((const float4*)(bres + r * D_))[tid];
    float4 v = make_float4(va.x + vb.x, va.y + vb.y, va.z + vb.z, va.w + vb.w);

    float s = v.x + v.y + v.z + v.w;
    float sq = v.x * v.x + v.y * v.y + v.z * v.z + v.w * v.w;

    __shared__ float s1[8], s2[8];
    const int w = tid >> 5, l = tid & 31;
    #pragma unroll
    for (int o = 16; o; o >>= 1) {
        s  += __shfl_xor_sync(~0u, s, o);
        sq += __shfl_xor_sync(~0u, sq, o);
    }
    if (l == 0) { s1[w] = s; s2[w] = sq; }
    __syncthreads();
    s  = (s1[0] + s1[1]) + (s1[2] + s1[3]) + (s1[4] + s1[5]) + (s1[6] + s1[7]);
    sq = (s2[0] + s2[1]) + (s2[2] + s2[3]) + (s2[4] + s2[5]) + (s2[6] + s2[7]);

    const float mean = s * (1.0f / D_);
    const float var = sq * (1.0f / D_) - mean * mean;
    const float rstd = rsqrtf(var + 1e-12f);

    float4 gg = ((const float4*)g)[tid];
    float4 bb = ((const float4*)beta)[tid];
    float4 o;
    o.x = gg.x * (v.x - mean) * rstd + bb.x;
    o.y = gg.y * (v.y - mean) * rstd + bb.y;
    o.z = gg.z * (v.z - mean) * rstd + bb.z;
    o.w = gg.w * (v.w - mean) * rstd + bb.w;
    ((float4*)(out + r * D_))[tid] = o;
}

// ---------------------------------------------------------------------------
extern "C" void kernel_launch(void* const* d_in, const int* in_sizes, int n_in,
                              void* d_out, int out_size)
{
    const float* x    = (const float*)d_in[0];
    const int*   mask = (const int*)  d_in[1];
    const float* Wq   = (const float*)d_in[2];
    const float* bq   = (const float*)d_in[3];
    const float* Wo   = (const float*)d_in[4];
    const float* bo   = (const float*)d_in[5];
    const float* W1   = (const float*)d_in[6];
    const float* b1   = (const float*)d_in[7];
    const float* W2   = (const float*)d_in[8];
    const float* b2   = (const float*)d_in[9];
    const float* g1   = (const float*)d_in[10];
    const float* be1  = (const float*)d_in[11];
    const float* g2   = (const float*)d_in[12];
    const float* be2  = (const float*)d_in[13];

    float* out2 = (float*)d_out;
    float* attn = out2 + (size_t)ROWS_ * D_;   // attn_weights region of d_out

    float *q, *attn_out, *proj, *out1, *ff1;
    cudaGetSymbolAddress((void**)&q,        g_q);
    cudaGetSymbolAddress((void**)&attn_out, g_attn_out);
    cudaGetSymbolAddress((void**)&proj,     g_proj);
    cudaGetSymbolAddress((void**)&out1,     g_out1);
    cudaGetSymbolAddress((void**)&ff1,      g_ff1);

    dim3 blk(256);

    // 1) q = k = v = x @ Wq + bq
    sgemm_nn<0><<<dim3(D_/128, ROWS_/128), blk>>>(x, D_, Wq, D_, q, D_, D_, bq);

    // 2) scores = (Q @ Q^T) / 8  -> attn region of d_out
    sgemm_scores<<<dim3(S_/128, S_/128, BH_), blk>>>(q, attn);

    // 3) masked softmax in place
    softmax_kernel<<<dim3(S_, BH_), blk>>>(attn, mask);

    // 4) attn_out = P @ V
    sgemm_pv<<<dim3(1, S_/128, BH_), blk>>>(attn, q, attn_out);

    // 5) proj = attn_out @ Wo + bo
    sgemm_nn<0><<<dim3(D_/128, ROWS_/128), blk>>>(attn_out, D_, Wo, D_, proj, D_, D_, bo);

    // 6) out1 = LN(x + proj)
    add_ln_kernel<<<ROWS_, blk>>>(x, proj, g1, be1, out1);

    // 7) ff1 = relu(out1 @ W1 + b1)
    sgemm_nn<1><<<dim3(DFF_/128, ROWS_/128), blk>>>(out1, D_, W1, DFF_, ff1, DFF_, D_, b1);

    // 8) ff2 = ff1 @ W2 + b2 (reuse proj buffer)
    sgemm_nn<0><<<dim3(D_/128, ROWS_/128), blk>>>(ff1, DFF_, W2, D_, proj, D_, DFF_, b2);

    // 9) out2 = LN(out1 + ff2) -> front of d_out
    add_ln_kernel<<<ROWS_, blk>>>(out1, proj, g2, be2, out2);
}

// round 2
// speedup vs baseline: 2.7514x; 2.7514x over previous
#include <cuda_runtime.h>
#include <cstdint>
#include <cstddef>

// ---------------------------------------------------------------------------
// EncoderLayer: B=4, S=1024, D=1024, H=16, HD=64, DFF=4096, fp32 in/out.
// TF32 tensor-core GEMMs (mma.sync.m16n8k8), fp32 accumulate.
// q==k==v (reference projects all through Wq).
// ---------------------------------------------------------------------------

#define B_  4
#define S_  1024
#define D_  1024
#define H_  16
#define HD_ 64
#define DFF_ 4096
#define ROWS_ (B_*S_)          // 4096
#define BH_ (B_*H_)            // 64

__device__ float g_q[ROWS_ * D_];
__device__ float g_attn_out[ROWS_ * D_];
__device__ float g_proj[ROWS_ * D_];
__device__ float g_out1[ROWS_ * D_];
__device__ float g_ff1[(size_t)ROWS_ * DFF_];

__device__ __forceinline__ float to_tf32(float x) {
    unsigned u;
    asm("cvt.rna.tf32.f32 %0, %1;" : "=r"(u) : "f"(x));
    return __uint_as_float(u);
}

__device__ __forceinline__ void mma8(float c[4], const float a[4], const float b[2]) {
    asm volatile(
        "mma.sync.aligned.m16n8k8.row.col.f32.tf32.tf32.f32 "
        "{%0,%1,%2,%3}, {%4,%5,%6,%7}, {%8,%9}, {%0,%1,%2,%3};\n"
        : "+f"(c[0]), "+f"(c[1]), "+f"(c[2]), "+f"(c[3])
        : "r"(__float_as_uint(a[0])), "r"(__float_as_uint(a[1])),
          "r"(__float_as_uint(a[2])), "r"(__float_as_uint(a[3])),
          "r"(__float_as_uint(b[0])), "r"(__float_as_uint(b[1])));
}

// ---------------------------------------------------------------------------
// Core NN GEMM: C[M,N] = A[M,K] @ B[K,N] (+bias)(relu). BM=128, BK=16.
// BN/WM/WN template; 256 threads; double-buffered smem; tf32 mma.
// All call-site shapes are exact multiples (no bounds checks needed).
// ---------------------------------------------------------------------------
template<int BN, int WM, int WN, int RELU, int BIAS>
__device__ __forceinline__ void gemm_core_nn(
    const float* __restrict__ A, int lda,
    const float* __restrict__ Bm, int ldb,
    float* __restrict__ C, int ldc,
    int K, const float* __restrict__ bias)
{
    constexpr int BM = 128, BK = 16;
    constexpr int WARPS_N = BN / WN;
    constexpr int MT = WM / 16, NT = WN / 8;
    constexpr int BROW = BN + 4;

    __shared__ float As[2][BM][20];     // [k-pad 20] rows
    __shared__ float Bs[2][BK][BROW];

    const int tid = threadIdx.x;
    const int lane = tid & 31, warp = tid >> 5;
    const int wm = (warp / WARPS_N) * WM;
    const int wn = (warp % WARPS_N) * WN;
    const int g = lane >> 2, tig = lane & 3;

    const int bm = blockIdx.y * BM;
    const int bn = blockIdx.x * BN;

    const int ar  = tid >> 2;           // 0..63
    const int akq = (tid & 3) * 4;      // 0,4,8,12
    const int br  = tid >> 4;           // 0..15
    const int bc  = (tid & 15) * 4;     // 0..60

    const float* Ap  = A + (size_t)(bm + ar) * lda + akq;
    const float* Ap2 = Ap + (size_t)64 * lda;
    const float* Bp  = Bm + (size_t)br * ldb + bn + bc;

    float4 pa0, pa1, pb0, pb1;

    auto gload = [&](int kk) {
        pa0 = *(const float4*)(Ap + kk);
        pa1 = *(const float4*)(Ap2 + kk);
        pb0 = *(const float4*)(Bp + (size_t)kk * ldb);
        if constexpr (BN == 128)
            pb1 = *(const float4*)(Bp + (size_t)kk * ldb + 64);
    };
    auto sstore = [&](int s) {
        *(float4*)&As[s][ar][akq] = make_float4(
            to_tf32(pa0.x), to_tf32(pa0.y), to_tf32(pa0.z), to_tf32(pa0.w));
        *(float4*)&As[s][ar + 64][akq] = make_float4(
            to_tf32(pa1.x), to_tf32(pa1.y), to_tf32(pa1.z), to_tf32(pa1.w));
        *(float4*)&Bs[s][br][bc] = make_float4(
            to_tf32(pb0.x), to_tf32(pb0.y), to_tf32(pb0.z), to_tf32(pb0.w));
        if constexpr (BN == 128)
            *(float4*)&Bs[s][br][bc + 64] = make_float4(
                to_tf32(pb1.x), to_tf32(pb1.y), to_tf32(pb1.z), to_tf32(pb1.w));
    };

    float acc[MT][NT][4] = {};

    gload(0); sstore(0); __syncthreads();
    const int nk = K / BK;
    for (int t = 0; t < nk; t++) {
        const int s = t & 1;
        if (t + 1 < nk) gload((t + 1) * BK);
        #pragma unroll
        for (int k0 = 0; k0 < BK; k0 += 8) {
            float af[MT][4], bf[NT][2];
            #pragma unroll
            for (int i = 0; i < MT; i++) {
                const int r0 = wm + i * 16 + g;
                af[i][0] = As[s][r0][k0 + tig];
                af[i][1] = As[s][r0 + 8][k0 + tig];
                af[i][2] = As[s][r0][k0 + tig + 4];
                af[i][3] = As[s][r0 + 8][k0 + tig + 4];
            }
            #pragma unroll
            for (int j = 0; j < NT; j++) {
                const int c0 = wn + j * 8 + g;
                bf[j][0] = Bs[s][k0 + tig][c0];
                bf[j][1] = Bs[s][k0 + tig + 4][c0];
            }
            #pragma unroll
            for (int i = 0; i < MT; i++)
                #pragma unroll
                for (int j = 0; j < NT; j++)
                    mma8(acc[i][j], af[i], bf[j]);
        }
        if (t + 1 < nk) sstore((t + 1) & 1);
        __syncthreads();
    }

    #pragma unroll
    for (int i = 0; i < MT; i++) {
        #pragma unroll
        for (int j = 0; j < NT; j++) {
            const int col = bn + wn + j * 8 + tig * 2;
            float2 v0 = make_float2(acc[i][j][0], acc[i][j][1]);
            float2 v1 = make_float2(acc[i][j][2], acc[i][j][3]);
            if (BIAS) {
                float2 bb = *(const float2*)(bias + col);
                v0.x += bb.x; v0.y += bb.y; v1.x += bb.x; v1.y += bb.y;
            }
            if (RELU) {
                v0.x = fmaxf(v0.x, 0.f); v0.y = fmaxf(v0.y, 0.f);
                v1.x = fmaxf(v1.x, 0.f); v1.y = fmaxf(v1.y, 0.f);
            }
            const int r0 = bm + wm + i * 16 + g;
            *(float2*)(C + (size_t)r0 * ldc + col) = v0;
            *(float2*)(C + (size_t)(r0 + 8) * ldc + col) = v1;
        }
    }
}

template<int BN, int WM, int WN, int RELU, int BIAS>
__global__ __launch_bounds__(256, 2) void k_gemm_nn(
    const float* __restrict__ A, int lda,
    const float* __restrict__ Bm, int ldb,
    float* __restrict__ C, int ldc,
    int K, const float* __restrict__ bias)
{
    gemm_core_nn<BN, WM, WN, RELU, BIAS>(A, lda, Bm, ldb, C, ldc, K, bias);
}

// PV: per head z, C[S,64] = P[S,S] @ Vhead[S,64] (head slices strided by D_)
__global__ __launch_bounds__(256, 2) void k_pv(
    const float* __restrict__ attn, const float* __restrict__ qbuf,
    float* __restrict__ out)
{
    const int z = blockIdx.z;
    const int b = z >> 4, h = z & 15;
    const size_t hoff = (size_t)b * S_ * D_ + (size_t)h * HD_;
    gemm_core_nn<64, 32, 32, 0, 0>(
        attn + (size_t)z * S_ * S_, S_,
        qbuf + hoff, D_,
        out + hoff, D_,
        S_, nullptr);
}

// ---------------------------------------------------------------------------
// Scores (NT): per head z, C = (Qh @ Qh^T) * 0.125. Qh: [S,64] strided D_.
// ---------------------------------------------------------------------------
__global__ __launch_bounds__(256, 2) void k_scores(
    const float* __restrict__ qbuf, float* __restrict__ attn)
{
    constexpr int BM = 128, BK = 16, WM = 64, WN = 32, WARPS_N = 4, MT = 4, NT = 4;
    __shared__ float As[2][BM][20];
    __shared__ float Bs[2][BM][20];

    const int z = blockIdx.z;
    const int b = z >> 4, h = z & 15;
    const float* Q = qbuf + (size_t)b * S_ * D_ + (size_t)h * HD_;
    float* C = attn + (size_t)z * S_ * S_;

    const int tid = threadIdx.x, lane = tid & 31, warp = tid >> 5;
    const int wm = (warp / WARPS_N) * WM, wn = (warp % WARPS_N) * WN;
    const int g = lane >> 2, tig = lane & 3;
    const int bm = blockIdx.y * BM, bn = blockIdx.x * BM;

    const int ar = tid >> 2, akq = (tid & 3) * 4;
    const float* Ap  = Q + (size_t)(bm + ar) * D_ + akq;
    const float* Ap2 = Ap + (size_t)64 * D_;
    const float* Bp  = Q + (size_t)(bn + ar) * D_ + akq;
    const float* Bp2 = Bp + (size_t)64 * D_;

    float4 pa0, pa1, pb0, pb1;
    auto gload = [&](int kk) {
        pa0 = *(const float4*)(Ap + kk);
        pa1 = *(const float4*)(Ap2 + kk);
        pb0 = *(const float4*)(Bp + kk);
        pb1 = *(const float4*)(Bp2 + kk);
    };
    auto sstore = [&](int s) {
        *(float4*)&As[s][ar][akq] = make_float4(
            to_tf32(pa0.x), to_tf32(pa0.y), to_tf32(pa0.z), to_tf32(pa0.w));
        *(float4*)&As[s][ar + 64][akq] = make_float4(
            to_tf32(pa1.x), to_tf32(pa1.y), to_tf32(pa1.z), to_tf32(pa1.w));
        *(float4*)&Bs[s][ar][akq] = make_float4(
            to_tf32(pb0.x), to_tf32(pb0.y), to_tf32(pb0.z), to_tf32(pb0.w));
        *(float4*)&Bs[s][ar + 64][akq] = make_float4(
            to_tf32(pb1.x), to_tf32(pb1.y), to_tf32(pb1.z), to_tf32(pb1.w));
    };

    float acc[MT][NT][4] = {};
    gload(0); sstore(0); __syncthreads();
    const int nk = HD_ / BK;    // 4
    for (int t = 0; t < nk; t++) {
        const int s = t & 1;
        if (t + 1 < nk) gload((t + 1) * BK);
        #pragma unroll
        for (int k0 = 0; k0 < BK; k0 += 8) {
            float af[MT][4], bf[NT][2];
            #pragma unroll
            for (int i = 0; i < MT; i++) {
                const int r0 = wm + i * 16 + g;
                af[i][0] = As[s][r0][k0 + tig];
                af[i][1] = As[s][r0 + 8][k0 + tig];
                af[i][2] = As[s][r0][k0 + tig + 4];
                af[i][3] = As[s][r0 + 8][k0 + tig + 4];
            }
            #pragma unroll
            for (int j = 0; j < NT; j++) {
                const int c0 = wn + j * 8 + g;
                bf[j][0] = Bs[s][c0][k0 + tig];
                bf[j][1] = Bs[s][c0][k0 + tig + 4];
            }
            #pragma unroll
            for (int i = 0; i < MT; i++)
                #pragma unroll
                for (int j = 0; j < NT; j++)
                    mma8(acc[i][j], af[i], bf[j]);
        }
        if (t + 1 < nk) sstore((t + 1) & 1);
        __syncthreads();
    }

    #pragma unroll
    for (int i = 0; i < MT; i++) {
        #pragma unroll
        for (int j = 0; j < NT; j++) {
            const int col = bn + wn + j * 8 + tig * 2;
            const int r0 = bm + wm + i * 16 + g;
            float2 v0 = make_float2(acc[i][j][0] * 0.125f, acc[i][j][1] * 0.125f);
            float2 v1 = make_float2(acc[i][j][2] * 0.125f, acc[i][j][3] * 0.125f);
            *(float2*)(C + (size_t)r0 * S_ + col) = v0;
            *(float2*)(C + (size_t)(r0 + 8) * S_ + col) = v1;
        }
    }
}

// ---------------------------------------------------------------------------
// Masked softmax, row-wise in place. grid = (S_, B*H), 256 threads.
// ---------------------------------------------------------------------------
__global__ __launch_bounds__(256) void softmax_kernel(
    float* __restrict__ attn, const int* __restrict__ mask)
{
    const int q = blockIdx.x;
    const int z = blockIdx.y;
    const int b = z >> 4;
    float* row = attn + (size_t)z * S_ * S_ + (size_t)q * S_;
    const int* mrow = mask + (size_t)b * S_ * S_ + (size_t)q * S_;
    const int tid = threadIdx.x;

    float4 v = ((const float4*)row)[tid];
    int4 m = ((const int4*)mrow)[tid];
    if (m.x == 0) v.x = -1e9f;
    if (m.y == 0) v.y = -1e9f;
    if (m.z == 0) v.z = -1e9f;
    if (m.w == 0) v.w = -1e9f;

    __shared__ float sred[8];
    const int w = tid >> 5, l = tid & 31;

    float mx = fmaxf(fmaxf(v.x, v.y), fmaxf(v.z, v.w));
    #pragma unroll
    for (int o = 16; o; o >>= 1) mx = fmaxf(mx, __shfl_xor_sync(~0u, mx, o));
    if (l == 0) sred[w] = mx;
    __syncthreads();
    mx = fmaxf(fmaxf(fmaxf(sred[0], sred[1]), fmaxf(sred[2], sred[3])),
               fmaxf(fmaxf(sred[4], sred[5]), fmaxf(sred[6], sred[7])));
    __syncthreads();

    v.x = __expf(v.x - mx);
    v.y = __expf(v.y - mx);
    v.z = __expf(v.z - mx);
    v.w = __expf(v.w - mx);

    float s = v.x + v.y + v.z + v.w;
    #pragma unroll
    for (int o = 16; o; o >>= 1) s += __shfl_xor_sync(~0u, s, o);
    if (l == 0) sred[w] = s;
    __syncthreads();
    s = (sred[0] + sred[1]) + (sred[2] + sred[3]) +
        (sred[4] + sred[5]) + (sred[6] + sred[7]);

    const float inv = 1.0f / s;
    v.x *= inv; v.y *= inv; v.z *= inv; v.w *= inv;
    ((float4*)row)[tid] = v;
}

// ---------------------------------------------------------------------------
// Fused residual add + LayerNorm. One block per row.
// ---------------------------------------------------------------------------
__global__ __launch_bounds__(256) void add_ln_kernel(
    const float* __restrict__ a, const float* __restrict__ bres,
    const float* __restrict__ g, const float* __restrict__ beta,
    float* __restrict__ out)
{
    const size_t r = blockIdx.x;
    const int tid = threadIdx.x;
    float4 va = ((const float4*)(a + r * D_))[tid];
    float4 vb = ((const float4*)(bres + r * D_))[tid];
    float4 v = make_float4(va.x + vb.x, va.y + vb.y, va.z + vb.z, va.w + vb.w);

    float s = v.x + v.y + v.z + v.w;
    float sq = v.x * v.x + v.y * v.y + v.z * v.z + v.w * v.w;

    __shared__ float s1[8], s2[8];
    const int w = tid >> 5, l = tid & 31;
    #pragma unroll
    for (int o = 16; o; o >>= 1) {
        s  += __shfl_xor_sync(~0u, s, o);
        sq += __shfl_xor_sync(~0u, sq, o);
    }
    if (l == 0) { s1[w] = s; s2[w] = sq; }
    __syncthreads();
    s  = (s1[0] + s1[1]) + (s1[2] + s1[3]) + (s1[4] + s1[5]) + (s1[6] + s1[7]);
    sq = (s2[0] + s2[1]) + (s2[2] + s2[3]) + (s2[4] + s2[5]) + (s2[6] + s2[7]);

    const float mean = s * (1.0f / D_);
    const float var = sq * (1.0f / D_) - mean * mean;
    const float rstd = rsqrtf(var + 1e-12f);

    float4 gg = ((const float4*)g)[tid];
    float4 bb = ((const float4*)beta)[tid];
    float4 o;
    o.x = gg.x * (v.x - mean) * rstd + bb.x;
    o.y = gg.y * (v.y - mean) * rstd + bb.y;
    o.z = gg.z * (v.z - mean) * rstd + bb.z;
    o.w = gg.w * (v.w - mean) * rstd + bb.w;
    ((float4*)(out + r * D_))[tid] = o;
}

// ---------------------------------------------------------------------------
extern "C" void kernel_launch(void* const* d_in, const int* in_sizes, int n_in,
                              void* d_out, int out_size)
{
    const float* x    = (const float*)d_in[0];
    const int*   mask = (const int*)  d_in[1];
    const float* Wq   = (const float*)d_in[2];
    const float* bq   = (const float*)d_in[3];
    const float* Wo   = (const float*)d_in[4];
    const float* bo   = (const float*)d_in[5];
    const float* W1   = (const float*)d_in[6];
    const float* b1   = (const float*)d_in[7];
    const float* W2   = (const float*)d_in[8];
    const float* b2   = (const float*)d_in[9];
    const float* g1   = (const float*)d_in[10];
    const float* be1  = (const float*)d_in[11];
    const float* g2   = (const float*)d_in[12];
    const float* be2  = (const float*)d_in[13];

    float* out2 = (float*)d_out;
    float* attn = out2 + (size_t)ROWS_ * D_;

    float *q, *attn_out, *proj, *out1, *ff1;
    cudaGetSymbolAddress((void**)&q,        g_q);
    cudaGetSymbolAddress((void**)&attn_out, g_attn_out);
    cudaGetSymbolAddress((void**)&proj,     g_proj);
    cudaGetSymbolAddress((void**)&out1,     g_out1);
    cudaGetSymbolAddress((void**)&ff1,      g_ff1);

    dim3 blk(256);

    // 1) q = k = v = x @ Wq + bq
    k_gemm_nn<128, 64, 32, 0, 1><<<dim3(D_ / 128, ROWS_ / 128), blk>>>(
        x, D_, Wq, D_, q, D_, D_, bq);

    // 2) scores = (Q @ Q^T) / 8  -> attn region of d_out
    k_scores<<<dim3(S_ / 128, S_ / 128, BH_), blk>>>(q, attn);

    // 3) masked softmax in place
    softmax_kernel<<<dim3(S_, BH_), blk>>>(attn, mask);

    // 4) attn_out = P @ V
    k_pv<<<dim3(1, S_ / 128, BH_), blk>>>(attn, q, attn_out);

    // 5) proj = attn_out @ Wo + bo
    k_gemm_nn<128, 64, 32, 0, 1><<<dim3(D_ / 128, ROWS_ / 128), blk>>>(
        attn_out, D_, Wo, D_, proj, D_, D_, bo);

    // 6) out1 = LN(x + proj)
    add_ln_kernel<<<ROWS_, blk>>>(x, proj, g1, be1, out1);

    // 7) ff1 = relu(out1 @ W1 + b1)
    k_gemm_nn<128, 64, 32, 1, 1><<<dim3(DFF_ / 128, ROWS_ / 128), blk>>>(
        out1, D_, W1, DFF_, ff1, DFF_, D_, b1);

    // 8) ff2 = ff1 @ W2 + b2 (reuse proj buffer)
    k_gemm_nn<128, 64, 32, 0, 1><<<dim3(D_ / 128, ROWS_ / 128), blk>>>(
        ff1, DFF_, W2, D_, proj, D_, DFF_, b2);

    // 9) out2 = LN(out1 + ff2) -> front of d_out
    add_ln_kernel<<<ROWS_, blk>>>(out1, proj, g2, be2, out2);
}

// round 3
// speedup vs baseline: 2.7816x; 1.0110x over previous
#include <cuda_runtime.h>
#include <cstdint>
#include <cstddef>

// ---------------------------------------------------------------------------
// EncoderLayer B=4,S=1024,D=1024,H=16,HD=64,DFF=4096 fp32.
// TF32 mma GEMMs (cp.async 3-stage) + fused attention (scores+softmax+PV).
// q==k==v (reference projects all through Wq).
// ---------------------------------------------------------------------------

#define B_  4
#define S_  1024
#define D_  1024
#define H_  16
#define HD_ 64
#define DFF_ 4096
#define ROWS_ (B_*S_)
#define BH_ (B_*H_)

__device__ float g_q[ROWS_ * D_];
__device__ float g_attn_out[ROWS_ * D_];
__device__ float g_proj[ROWS_ * D_];
__device__ float g_out1[ROWS_ * D_];
__device__ float g_ff1[(size_t)ROWS_ * DFF_];

__device__ __forceinline__ float to_tf32(float x) {
    unsigned u; asm("cvt.rna.tf32.f32 %0, %1;" : "=r"(u) : "f"(x));
    return __uint_as_float(u);
}
__device__ __forceinline__ void mma8(float c[4], const float a[4], const float b[2]) {
    asm volatile(
        "mma.sync.aligned.m16n8k8.row.col.f32.tf32.tf32.f32 "
        "{%0,%1,%2,%3}, {%4,%5,%6,%7}, {%8,%9}, {%0,%1,%2,%3};\n"
        : "+f"(c[0]), "+f"(c[1]), "+f"(c[2]), "+f"(c[3])
        : "r"(__float_as_uint(a[0])), "r"(__float_as_uint(a[1])),
          "r"(__float_as_uint(a[2])), "r"(__float_as_uint(a[3])),
          "r"(__float_as_uint(b[0])), "r"(__float_as_uint(b[1])));
}
__device__ __forceinline__ unsigned smem_u32(const void* p) {
    return (unsigned)__cvta_generic_to_shared(p);
}
__device__ __forceinline__ void cpa16(unsigned dst, const float* src) {
    asm volatile("cp.async.cg.shared.global [%0], [%1], 16;" :: "r"(dst), "l"(src));
}
__device__ __forceinline__ void cp_commit() {
    asm volatile("cp.async.commit_group;");
}
template<int N> __device__ __forceinline__ void cp_wait() {
    asm volatile("cp.async.wait_group %0;" :: "n"(N));
}

// ---------------------------------------------------------------------------
// Pipelined NN GEMM: C[M,N] = A[M,K]@B[K,N] + bias (opt relu).
// BM=BN=128, BK=16, 256 threads, 3-stage cp.async, tf32 mma, cvt at consume.
// ---------------------------------------------------------------------------
#define GEMM_SMEM (3 * (128*20 + 16*136) * 4)

template<int RELU>
__global__ __launch_bounds__(256, 2) void k_gemm(
    const float* __restrict__ A, int lda,
    const float* __restrict__ Bm, int ldb,
    float* __restrict__ C, int ldc,
    int K, const float* __restrict__ bias)
{
    constexpr int ST = 3;
    extern __shared__ float sm[];
    float (*As)[128][20] = reinterpret_cast<float(*)[128][20]>(sm);
    float (*Bs)[16][136] = reinterpret_cast<float(*)[16][136]>(sm + ST * 128 * 20);

    const int tid = threadIdx.x, lane = tid & 31, warp = tid >> 5;
    const int wm = (warp >> 2) * 64, wn = (warp & 3) * 32;
    const int g = lane >> 2, tig = lane & 3;
    const int bm = blockIdx.y * 128, bn = blockIdx.x * 128;

    const int ar = tid >> 2, akq = (tid & 3) * 4;
    const int br = tid >> 4, bc = (tid & 15) * 4;

    const float* Ag  = A + (size_t)(bm + ar) * lda + akq;
    const float* Ag2 = Ag + (size_t)64 * lda;
    const float* Bg  = Bm + (size_t)br * ldb + bn + bc;

    auto issue = [&](int s, int kk) {
        cpa16(smem_u32(&As[s][ar][akq]),    Ag + kk);
        cpa16(smem_u32(&As[s][ar + 64][akq]), Ag2 + kk);
        cpa16(smem_u32(&Bs[s][br][bc]),     Bg + (size_t)kk * ldb);
        cpa16(smem_u32(&Bs[s][br][bc + 64]), Bg + (size_t)kk * ldb + 64);
        cp_commit();
    };

    float acc[4][4][4] = {};
    const int nk = K / 16;
    issue(0, 0);
    issue(1, 16);

    for (int t = 0; t < nk; t++) {
        cp_wait<ST - 2>();
        __syncthreads();
        if (t + 2 < nk) issue((t + 2) % ST, (t + 2) * 16);
        const int s = t % ST;
        #pragma unroll
        for (int k0 = 0; k0 < 16; k0 += 8) {
            float af[4][4], bf[4][2];
            #pragma unroll
            for (int i = 0; i < 4; i++) {
                const int r0 = wm + i * 16 + g;
                af[i][0] = to_tf32(As[s][r0][k0 + tig]);
                af[i][1] = to_tf32(As[s][r0 + 8][k0 + tig]);
                af[i][2] = to_tf32(As[s][r0][k0 + tig + 4]);
                af[i][3] = to_tf32(As[s][r0 + 8][k0 + tig + 4]);
            }
            #pragma unroll
            for (int j = 0; j < 4; j++) {
                const int c0 = wn + j * 8 + g;
                bf[j][0] = to_tf32(Bs[s][k0 + tig][c0]);
                bf[j][1] = to_tf32(Bs[s][k0 + tig + 4][c0]);
            }
            #pragma unroll
            for (int i = 0; i < 4; i++)
                #pragma unroll
                for (int j = 0; j < 4; j++)
                    mma8(acc[i][j], af[i], bf[j]);
        }
        __syncthreads();
    }

    #pragma unroll
    for (int i = 0; i < 4; i++) {
        #pragma unroll
        for (int j = 0; j < 4; j++) {
            const int col = bn + wn + j * 8 + tig * 2;
            float2 bb = *(const float2*)(bias + col);
            float2 v0 = make_float2(acc[i][j][0] + bb.x, acc[i][j][1] + bb.y);
            float2 v1 = make_float2(acc[i][j][2] + bb.x, acc[i][j][3] + bb.y);
            if (RELU) {
                v0.x = fmaxf(v0.x, 0.f); v0.y = fmaxf(v0.y, 0.f);
                v1.x = fmaxf(v1.x, 0.f); v1.y = fmaxf(v1.y, 0.f);
            }
            const int r0 = bm + wm + i * 16 + g;
            *(float2*)(C + (size_t)r0 * ldc + col) = v0;
            *(float2*)(C + (size_t)(r0 + 8) * ldc + col) = v1;
        }
    }
}

// ---------------------------------------------------------------------------
// Fused attention: per (q-block of 128, head z):
// sweep1: row sums of masked exp(QK/8); sweep2: normalized weights -> gmem,
// P@V accumulated -> attn_out. q==k==v head slice, stride D_.
// ---------------------------------------------------------------------------
#define Q_STR  68
#define T_STR  76
#define P_STR  140
#define ATTN_SMEM ((128*Q_STR + 2*128*T_STR + 128*P_STR + 5*128) * 4)

__global__ __launch_bounds__(256, 1) void k_attn(
    const float* __restrict__ qbuf, const int* __restrict__ mask,
    float* __restrict__ attnw, float* __restrict__ aout)
{
    extern __shared__ float sm[];
    float (*Qs)[Q_STR] = reinterpret_cast<float(*)[Q_STR]>(sm);
    float (*Ts)[128][T_STR] =
        reinterpret_cast<float(*)[128][T_STR]>(sm + 128 * Q_STR);
    float (*Ps)[P_STR] =
        reinterpret_cast<float(*)[P_STR]>(sm + 128 * Q_STR + 2 * 128 * T_STR);
    float* rs   = sm + 128 * Q_STR + 2 * 128 * T_STR + 128 * P_STR;  // [4][128]
    float* rinv = rs + 4 * 128;                                       // [128]

    const int tid = threadIdx.x, lane = tid & 31, warp = tid >> 5;
    const int g = lane >> 2, tig = lane & 3;
    const int wm = (warp >> 2) * 64, wn = (warp & 3) * 32, wnp = (warp & 3) * 16;
    const int qb = blockIdx.x, z = blockIdx.y;
    const int b = z >> 4, h = z & 15;
    const float* hs = qbuf + (size_t)b * S_ * D_ + h * HD_;
    const int bm = qb * 128;

    // load Q tile (tf32-converted once)
    {
        const int r = tid >> 1, cb = (tid & 1) * 32;
        const float* src = hs + (size_t)(bm + r) * D_ + cb;
        #pragma unroll
        for (int i = 0; i < 8; i++) {
            float4 v = *(const float4*)(src + i * 4);
            *(float4*)&Qs[r][cb + i * 4] = make_float4(
                to_tf32(v.x), to_tf32(v.y), to_tf32(v.z), to_tf32(v.w));
        }
    }

    const int lr = tid >> 1, lcb = (tid & 1) * 32;
    auto issueT = [&](int buf, int ck) {
        const float* src = hs + (size_t)(ck * 128 + lr) * D_ + lcb;
        #pragma unroll
        for (int i = 0; i < 8; i++)
            cpa16(smem_u32(&Ts[buf][lr][lcb + i * 4]), src + i * 4);
        cp_commit();
    };

    issueT(0, 0);
    __syncthreads();

    const int* mbase = mask + (size_t)b * S_ * S_;

    float psum0[4] = {}, psum1[4] = {};

    // ---------------- sweep 1: row sums ----------------
    for (int ck = 0; ck < 8; ck++) {
        cp_wait<0>();
        __syncthreads();
        if (ck + 1 < 8) issueT((ck + 1) & 1, ck + 1);
        const int ts = ck & 1;

        float acc[4][4][4] = {};
        #pragma unroll
        for (int k0 = 0; k0 < 64; k0 += 8) {
            float af[4][4], bf[4][2];
            #pragma unroll
            for (int i = 0; i < 4; i++) {
                const int r0 = wm + i * 16 + g;
                af[i][0] = Qs[r0][k0 + tig];
                af[i][1] = Qs[r0 + 8][k0 + tig];
                af[i][2] = Qs[r0][k0 + tig + 4];
                af[i][3] = Qs[r0 + 8][k0 + tig + 4];
            }
            #pragma unroll
            for (int j = 0; j < 4; j++) {
                const int c0 = wn + j * 8 + g;
                bf[j][0] = to_tf32(Ts[ts][c0][k0 + tig]);
                bf[j][1] = to_tf32(Ts[ts][c0][k0 + tig + 4]);
            }
            #pragma unroll
            for (int i = 0; i < 4; i++)
                #pragma unroll
                for (int j = 0; j < 4; j++)
                    mma8(acc[i][j], af[i], bf[j]);
        }

        #pragma unroll
        for (int i = 0; i < 4; i++) {
            const int r0 = bm + wm + i * 16 + g;
            #pragma unroll
            for (int j = 0; j < 4; j++) {
                const int c0 = ck * 128 + wn + j * 8 + tig * 2;
                int2 m0 = *(const int2*)(mbase + (size_t)r0 * S_ + c0);
                int2 m1 = *(const int2*)(mbase + (size_t)(r0 + 8) * S_ + c0);
                float e0 = m0.x ? __expf(acc[i][j][0] * 0.125f) : 0.f;
                float e1 = m0.y ? __expf(acc[i][j][1] * 0.125f) : 0.f;
                float e2 = m1.x ? __expf(acc[i][j][2] * 0.125f) : 0.f;
                float e3 = m1.y ? __expf(acc[i][j][3] * 0.125f) : 0.f;
                psum0[i] += e0 + e1;
                psum1[i] += e2 + e3;
            }
        }
    }

    #pragma unroll
    for (int i = 0; i < 4; i++) {
        psum0[i] += __shfl_xor_sync(~0u, psum0[i], 1);
        psum0[i] += __shfl_xor_sync(~0u, psum0[i], 2);
        psum1[i] += __shfl_xor_sync(~0u, psum1[i], 1);
        psum1[i] += __shfl_xor_sync(~0u, psum1[i], 2);
    }
    if (tig == 0) {
        #pragma unroll
        for (int i = 0; i < 4; i++) {
            rs[(warp & 3) * 128 + wm + i * 16 + g]     = psum0[i];
            rs[(warp & 3) * 128 + wm + i * 16 + g + 8] = psum1[i];
        }
    }
    issueT(0, 0);   // prefetch chunk 0 for sweep 2 (buf0 free: last used for chunk 6)
    __syncthreads();
    if (tid < 128)
        rinv[tid] = 1.0f / (rs[tid] + rs[128 + tid] + rs[256 + tid] + rs[384 + tid]);
    __syncthreads();

    // ---------------- sweep 2: weights out + PV ----------------
    float pv[4][2][4] = {};

    for (int ck = 0; ck < 8; ck++) {
        cp_wait<0>();
        __syncthreads();
        if (ck + 1 < 8) issueT((ck + 1) & 1, ck + 1);
        const int ts = ck & 1;

        float acc[4][4][4] = {};
        #pragma unroll
        for (int k0 = 0; k0 < 64; k0 += 8) {
            float af[4][4], bf[4][2];
            #pragma unroll
            for (int i = 0; i < 4; i++) {
                const int r0 = wm + i * 16 + g;
                af[i][0] = Qs[r0][k0 + tig];
                af[i][1] = Qs[r0 + 8][k0 + tig];
                af[i][2] = Qs[r0][k0 + tig + 4];
                af[i][3] = Qs[r0 + 8][k0 + tig + 4];
            }
            #pragma unroll
            for (int j = 0; j < 4; j++) {
                const int c0 = wn + j * 8 + g;
                bf[j][0] = to_tf32(Ts[ts][c0][k0 + tig]);
                bf[j][1] = to_tf32(Ts[ts][c0][k0 + tig + 4]);
            }
            #pragma unroll
            for (int i = 0; i < 4; i++)
                #pragma unroll
                for (int j = 0; j < 4; j++)
                    mma8(acc[i][j], af[i], bf[j]);
        }

        #pragma unroll
        for (int i = 0; i < 4; i++) {
            const int lr0 = wm + i * 16 + g;
            const int r0 = bm + lr0;
            const float v0 = rinv[lr0], v1 = rinv[lr0 + 8];
            #pragma unroll
            for (int j = 0; j < 4; j++) {
                const int lc = wn + j * 8 + tig * 2;
                const int c0 = ck * 128 + lc;
                int2 m0 = *(const int2*)(mbase + (size_t)r0 * S_ + c0);
                int2 m1 = *(const int2*)(mbase + (size_t)(r0 + 8) * S_ + c0);
                float e0 = m0.x ? __expf(acc[i][j][0] * 0.125f) * v0 : 0.f;
                float e1 = m0.y ? __expf(acc[i][j][1] * 0.125f) * v0 : 0.f;
                float e2 = m1.x ? __expf(acc[i][j][2] * 0.125f) * v1 : 0.f;
                float e3 = m1.y ? __expf(acc[i][j][3] * 0.125f) * v1 : 0.f;
                *(float2*)&Ps[lr0][lc]     = make_float2(to_tf32(e0), to_tf32(e1));
                *(float2*)&Ps[lr0 + 8][lc] = make_float2(to_tf32(e2), to_tf32(e3));
            }
        }
        __syncthreads();

        // PV accumulate: pv += Ps(128x128) @ V(128x64)
        #pragma unroll
        for (int k0 = 0; k0 < 128; k0 += 8) {
            float af[4][4], bf[2][2];
            #pragma unroll
            for (int i = 0; i < 4; i++) {
                const int r0 = wm + i * 16 + g;
                af[i][0] = Ps[r0][k0 + tig];
                af[i][1] = Ps[r0 + 8][k0 + tig];
                af[i][2] = Ps[r0][k0 + tig + 4];
                af[i][3] = Ps[r0 + 8][k0 + tig + 4];
            }
            #pragma unroll
            for (int j = 0; j < 2; j++) {
                const int c0 = wnp + j * 8 + g;
                bf[j][0] = to_tf32(Ts[ts][k0 + tig][c0]);
                bf[j][1] = to_tf32(Ts[ts][k0 + tig + 4][c0]);
            }
            #pragma unroll
            for (int i = 0; i < 4; i++)
                #pragma unroll
                for (int j = 0; j < 2; j++)
                    mma8(pv[i][j], af[i], bf[j]);
        }

        // copy normalized weights Ps -> gmem (coalesced)
        {
            const int c = (lane) * 4, rb = warp;
            #pragma unroll
            for (int rr = 0; rr < 16; rr++) {
                const int r = rb + rr * 8;
                float4 v = *(const float4*)&Ps[r][c];
                *(float4*)(attnw + ((size_t)z * S_ + bm + r) * S_ + ck * 128 + c) = v;
            }
        }
        __syncthreads();
    }

    // epilogue: attn_out
    #pragma unroll
    for (int i = 0; i < 4; i++) {
        const size_t gr0 = (size_t)(b * S_ + bm + wm + i * 16 + g);
        #pragma unroll
        for (int j = 0; j < 2; j++) {
            const int col = h * HD_ + wnp + j * 8 + tig * 2;
            *(float2*)(aout + gr0 * D_ + col) =
                make_float2(pv[i][j][0], pv[i][j][1]);
            *(float2*)(aout + (gr0 + 8) * D_ + col) =
                make_float2(pv[i][j][2], pv[i][j][3]);
        }
    }
}

// ---------------------------------------------------------------------------
// Fused residual add + LayerNorm.
// ---------------------------------------------------------------------------
__global__ __launch_bounds__(256) void add_ln_kernel(
    const float* __restrict__ a, const float* __restrict__ bres,
    const float* __restrict__ g, const float* __restrict__ beta,
    float* __restrict__ out)
{
    const size_t r = blockIdx.x;
    const int tid = threadIdx.x;
    float4 va = ((const float4*)(a + r * D_))[tid];
    float4 vb = ((const float4*)(bres + r * D_))[tid];
    float4 v = make_float4(va.x + vb.x, va.y + vb.y, va.z + vb.z, va.w + vb.w);

    float s = v.x + v.y + v.z + v.w;
    float sq = v.x * v.x + v.y * v.y + v.z * v.z + v.w * v.w;

    __shared__ float s1[8], s2[8];
    const int w = tid >> 5, l = tid & 31;
    #pragma unroll
    for (int o = 16; o; o >>= 1) {
        s  += __shfl_xor_sync(~0u, s, o);
        sq += __shfl_xor_sync(~0u, sq, o);
    }
    if (l == 0) { s1[w] = s; s2[w] = sq; }
    __syncthreads();
    s  = (s1[0] + s1[1]) + (s1[2] + s1[3]) + (s1[4] + s1[5]) + (s1[6] + s1[7]);
    sq = (s2[0] + s2[1]) + (s2[2] + s2[3]) + (s2[4] + s2[5]) + (s2[6] + s2[7]);

    const float mean = s * (1.0f / D_);
    const float var = sq * (1.0f / D_) - mean * mean;
    const float rstd = rsqrtf(var + 1e-12f);

    float4 gg = ((const float4*)g)[tid];
    float4 bb = ((const float4*)beta)[tid];
    float4 o;
    o.x = gg.x * (v.x - mean) * rstd + bb.x;
    o.y = gg.y * (v.y - mean) * rstd + bb.y;
    o.z = gg.z * (v.z - mean) * rstd + bb.z;
    o.w = gg.w * (v.w - mean) * rstd + bb.w;
    ((float4*)(out + r * D_))[tid] = o;
}

// ---------------------------------------------------------------------------
extern "C" void kernel_launch(void* const* d_in, const int* in_sizes, int n_in,
                              void* d_out, int out_size)
{
    const float* x    = (const float*)d_in[0];
    const int*   mask = (const int*)  d_in[1];
    const float* Wq   = (const float*)d_in[2];
    const float* bq   = (const float*)d_in[3];
    const float* Wo   = (const float*)d_in[4];
    const float* bo   = (const float*)d_in[5];
    const float* W1   = (const float*)d_in[6];
    const float* b1   = (const float*)d_in[7];
    const float* W2   = (const float*)d_in[8];
    const float* b2   = (const float*)d_in[9];
    const float* g1   = (const float*)d_in[10];
    const float* be1  = (const float*)d_in[11];
    const float* g2   = (const float*)d_in[12];
    const float* be2  = (const float*)d_in[13];

    float* out2 = (float*)d_out;
    float* attn = out2 + (size_t)ROWS_ * D_;

    float *q, *attn_out, *proj, *out1, *ff1;
    cudaGetSymbolAddress((void**)&q,        g_q);
    cudaGetSymbolAddress((void**)&attn_out, g_attn_out);
    cudaGetSymbolAddress((void**)&proj,     g_proj);
    cudaGetSymbolAddress((void**)&out1,     g_out1);
    cudaGetSymbolAddress((void**)&ff1,      g_ff1);

    cudaFuncSetAttribute((const void*)k_gemm<0>,
        cudaFuncAttributeMaxDynamicSharedMemorySize, GEMM_SMEM);
    cudaFuncSetAttribute((const void*)k_gemm<1>,
        cudaFuncAttributeMaxDynamicSharedMemorySize, GEMM_SMEM);
    cudaFuncSetAttribute((const void*)k_attn,
        cudaFuncAttributeMaxDynamicSharedMemorySize, ATTN_SMEM);

    dim3 blk(256);

    // 1) q = k = v = x @ Wq + bq
    k_gemm<0><<<dim3(D_ / 128, ROWS_ / 128), blk, GEMM_SMEM>>>(
        x, D_, Wq, D_, q, D_, D_, bq);

    // 2) fused attention: attn weights -> d_out, attn_out -> scratch
    k_attn<<<dim3(S_ / 128, BH_), blk, ATTN_SMEM>>>(q, mask, attn, attn_out);

    // 3) proj = attn_out @ Wo + bo
    k_gemm<0><<<dim3(D_ / 128, ROWS_ / 128), blk, GEMM_SMEM>>>(
        attn_out, D_, Wo, D_, proj, D_, D_, bo);

    // 4) out1 = LN(x + proj)
    add_ln_kernel<<<ROWS_, blk>>>(x, proj, g1, be1, out1);

    // 5) ff1 = relu(out1 @ W1 + b1)
    k_gemm<1><<<dim3(DFF_ / 128, ROWS_ / 128), blk, GEMM_SMEM>>>(
        out1, D_, W1, DFF_, ff1, DFF_, D_, b1);

    // 6) ff2 = ff1 @ W2 + b2
    k_gemm<0><<<dim3(D_ / 128, ROWS_ / 128), blk, GEMM_SMEM>>>(
        ff1, DFF_, W2, D_, proj, D_, DFF_, b2);

    // 7) out2 = LN(out1 + ff2)
    add_ln_kernel<<<ROWS_, blk>>>(out1, proj, g2, be2, out2);
}

// round 4
// speedup vs baseline: 2.8351x; 1.0192x over previous
#include <cuda_runtime.h>
#include <cstdint>
#include <cstddef>

// ---------------------------------------------------------------------------
// EncoderLayer B=4,S=1024,D=1024,H=16,HD=64,DFF=4096 fp32.
// TF32 mma GEMMs (cp.async, pre-rounded operands) + fused attention.
// q==k==v (reference projects all through Wq).
// ---------------------------------------------------------------------------

#define B_  4
#define S_  1024
#define D_  1024
#define H_  16
#define HD_ 64
#define DFF_ 4096
#define ROWS_ (B_*S_)
#define BH_ (B_*H_)

__device__ float g_q[ROWS_ * D_];
__device__ float g_attn_out[ROWS_ * D_];
__device__ float g_proj[ROWS_ * D_];
__device__ float g_out1[ROWS_ * D_];
__device__ float g_ff1[(size_t)ROWS_ * DFF_];
__device__ float g_wt[10 * 1024 * 1024];   // Wq_t(1M) Wo_t(1M) W1_t(4M) W2_t(4M)

__device__ __forceinline__ float to_tf32(float x) {
    unsigned u; asm("cvt.rna.tf32.f32 %0, %1;" : "=r"(u) : "f"(x));
    return __uint_as_float(u);
}
__device__ __forceinline__ void mma8(float c[4], const float a[4], const float b[2]) {
    asm volatile(
        "mma.sync.aligned.m16n8k8.row.col.f32.tf32.tf32.f32 "
        "{%0,%1,%2,%3}, {%4,%5,%6,%7}, {%8,%9}, {%0,%1,%2,%3};\n"
        : "+f"(c[0]), "+f"(c[1]), "+f"(c[2]), "+f"(c[3])
        : "r"(__float_as_uint(a[0])), "r"(__float_as_uint(a[1])),
          "r"(__float_as_uint(a[2])), "r"(__float_as_uint(a[3])),
          "r"(__float_as_uint(b[0])), "r"(__float_as_uint(b[1])));
}
__device__ __forceinline__ unsigned smem_u32(const void* p) {
    return (unsigned)__cvta_generic_to_shared(p);
}
__device__ __forceinline__ void cpa16(unsigned dst, const float* src) {
    asm volatile("cp.async.cg.shared.global [%0], [%1], 16;" :: "r"(dst), "l"(src));
}
__device__ __forceinline__ void cp_commit() {
    asm volatile("cp.async.commit_group;");
}
template<int N> __device__ __forceinline__ void cp_wait() {
    asm volatile("cp.async.wait_group %0;" :: "n"(N));
}

// ---------------------------------------------------------------------------
// tf32 pre-round pass (grid-stride, float4)
// ---------------------------------------------------------------------------
__global__ __launch_bounds__(256) void k_cvt(
    const float* __restrict__ src, float* __restrict__ dst, int n4)
{
    int i = blockIdx.x * 256 + threadIdx.x;
    if (i < n4) {
        float4 v = ((const float4*)src)[i];
        ((float4*)dst)[i] = make_float4(
            to_tf32(v.x), to_tf32(v.y), to_tf32(v.z), to_tf32(v.w));
    }
}

// ---------------------------------------------------------------------------
// Pipelined NN GEMM. BM=BN=128, BK=16, 256 threads, 3-stage cp.async.
// A/B assumed pre-rounded tf32 unless CVT_A. ROUND_C rounds output.
// ---------------------------------------------------------------------------
#define GEMM_SMEM (3 * (128*20 + 16*136) * 4)

template<int RELU, int CVT_A, int ROUND_C>
__global__ __launch_bounds__(256, 2) void k_gemm(
    const float* __restrict__ A, int lda,
    const float* __restrict__ Bm, int ldb,
    float* __restrict__ C, int ldc,
    int K, const float* __restrict__ bias)
{
    constexpr int ST = 3;
    extern __shared__ float sm[];
    float (*As)[128][20] = reinterpret_cast<float(*)[128][20]>(sm);
    float (*Bs)[16][136] = reinterpret_cast<float(*)[16][136]>(sm + ST * 128 * 20);

    const int tid = threadIdx.x, lane = tid & 31, warp = tid >> 5;
    const int wm = (warp >> 2) * 64, wn = (warp & 3) * 32;
    const int g = lane >> 2, tig = lane & 3;
    const int bm = blockIdx.y * 128, bn = blockIdx.x * 128;

    const int ar = tid >> 2, akq = (tid & 3) * 4;
    const int br = tid >> 4, bc = (tid & 15) * 4;

    const float* Ag  = A + (size_t)(bm + ar) * lda + akq;
    const float* Ag2 = Ag + (size_t)64 * lda;
    const float* Bg  = Bm + (size_t)br * ldb + bn + bc;

    auto issue = [&](int s, int kk) {
        cpa16(smem_u32(&As[s][ar][akq]),      Ag + kk);
        cpa16(smem_u32(&As[s][ar + 64][akq]), Ag2 + kk);
        cpa16(smem_u32(&Bs[s][br][bc]),       Bg + (size_t)kk * ldb);
        cpa16(smem_u32(&Bs[s][br][bc + 64]),  Bg + (size_t)kk * ldb + 64);
        cp_commit();
    };

    float acc[4][4][4] = {};
    const int nk = K / 16;
    issue(0, 0);
    issue(1, 16);

    for (int t = 0; t < nk; t++) {
        cp_wait<ST - 2>();
        __syncthreads();
        if (t + 2 < nk) issue((t + 2) % ST, (t + 2) * 16);
        const int s = t % ST;
        #pragma unroll
        for (int k0 = 0; k0 < 16; k0 += 8) {
            float af[4][4], bf[4][2];
            #pragma unroll
            for (int i = 0; i < 4; i++) {
                const int r0 = wm + i * 16 + g;
                if (CVT_A) {
                    af[i][0] = to_tf32(As[s][r0][k0 + tig]);
                    af[i][1] = to_tf32(As[s][r0 + 8][k0 + tig]);
                    af[i][2] = to_tf32(As[s][r0][k0 + tig + 4]);
                    af[i][3] = to_tf32(As[s][r0 + 8][k0 + tig + 4]);
                } else {
                    af[i][0] = As[s][r0][k0 + tig];
                    af[i][1] = As[s][r0 + 8][k0 + tig];
                    af[i][2] = As[s][r0][k0 + tig + 4];
                    af[i][3] = As[s][r0 + 8][k0 + tig + 4];
                }
            }
            #pragma unroll
            for (int j = 0; j < 4; j++) {
                const int c0 = wn + j * 8 + g;
                bf[j][0] = Bs[s][k0 + tig][c0];
                bf[j][1] = Bs[s][k0 + tig + 4][c0];
            }
            #pragma unroll
            for (int i = 0; i < 4; i++)
                #pragma unroll
                for (int j = 0; j < 4; j++)
                    mma8(acc[i][j], af[i], bf[j]);
        }
        __syncthreads();
    }

    #pragma unroll
    for (int i = 0; i < 4; i++) {
        #pragma unroll
        for (int j = 0; j < 4; j++) {
            const int col = bn + wn + j * 8 + tig * 2;
            float2 bb = *(const float2*)(bias + col);
            float2 v0 = make_float2(acc[i][j][0] + bb.x, acc[i][j][1] + bb.y);
            float2 v1 = make_float2(acc[i][j][2] + bb.x, acc[i][j][3] + bb.y);
            if (RELU) {
                v0.x = fmaxf(v0.x, 0.f); v0.y = fmaxf(v0.y, 0.f);
                v1.x = fmaxf(v1.x, 0.f); v1.y = fmaxf(v1.y, 0.f);
            }
            if (ROUND_C) {
                v0.x = to_tf32(v0.x); v0.y = to_tf32(v0.y);
                v1.x = to_tf32(v1.x); v1.y = to_tf32(v1.y);
            }
            const int r0 = bm + wm + i * 16 + g;
            *(float2*)(C + (size_t)r0 * ldc + col) = v0;
            *(float2*)(C + (size_t)(r0 + 8) * ldc + col) = v1;
        }
    }
}

// ---------------------------------------------------------------------------
// Fused attention, 512 threads. Per (128-q-block, head z):
// sweep1: masked-exp row sums; sweep2: normalized weights -> gmem + PV.
// q buffer is pre-rounded tf32 -> no cvt in mainloop.
// QK warp tile 32x32 (4x4 warps), PV warp tile 32x16.
// ---------------------------------------------------------------------------
#define Q_STR  68
#define T_STR  68
#define P_STR  132
#define ATTN_SMEM ((128*Q_STR + 2*128*T_STR + 128*P_STR + 4*128 + 128) * 4)

__global__ __launch_bounds__(512, 1) void k_attn(
    const float* __restrict__ qbuf, const int* __restrict__ mask,
    float* __restrict__ attnw, float* __restrict__ aout)
{
    extern __shared__ float sm[];
    float (*Qs)[Q_STR] = reinterpret_cast<float(*)[Q_STR]>(sm);
    float (*Ts)[128][T_STR] =
        reinterpret_cast<float(*)[128][T_STR]>(sm + 128 * Q_STR);
    float (*Ps)[P_STR] =
        reinterpret_cast<float(*)[P_STR]>(sm + 128 * Q_STR + 2 * 128 * T_STR);
    float* rs   = sm + 128 * Q_STR + 2 * 128 * T_STR + 128 * P_STR;  // [4][128]
    float* rinv = rs + 4 * 128;                                       // [128]

    const int tid = threadIdx.x, lane = tid & 31, warp = tid >> 5;
    const int g = lane >> 2, tig = lane & 3;
    const int wr = (warp >> 2) * 32;        // M offset (QK & PV)
    const int wc = warp & 3;                // N group
    const int wnq = wc * 32;                // QK N offset
    const int wnp = wc * 16;                // PV N offset
    const int qb = blockIdx.x, z = blockIdx.y;
    const int b = z >> 4, h = z & 15;
    const float* hs = qbuf + (size_t)b * S_ * D_ + h * HD_;
    const int bm = qb * 128;

    const int lr = tid >> 2, lcb = (tid & 3) * 16;

    // Q tile (pre-rounded tf32) via cp.async
    {
        const float* src = hs + (size_t)(bm + lr) * D_ + lcb;
        #pragma unroll
        for (int i = 0; i < 4; i++)
            cpa16(smem_u32(&Qs[lr][lcb + i * 4]), src + i * 4);
        cp_commit();
    }
    auto issueT = [&](int buf, int ck) {
        const float* src = hs + (size_t)(ck * 128 + lr) * D_ + lcb;
        #pragma unroll
        for (int i = 0; i < 4; i++)
            cpa16(smem_u32(&Ts[buf][lr][lcb + i * 4]), src + i * 4);
        cp_commit();
    };
    issueT(0, 0);
    cp_wait<0>();
    __syncthreads();

    const int* mbase = mask + (size_t)b * S_ * S_;

    // ---------------- sweep 1: row sums of masked exp ----------------
    float psum0[2] = {}, psum1[2] = {};
    for (int ck = 0; ck < 8; ck++) {
        const int ts = ck & 1;
        if (ck + 1 < 8) issueT(ts ^ 1, ck + 1);

        float acc[2][4][4] = {};
        #pragma unroll
        for (int k0 = 0; k0 < 64; k0 += 8) {
            float af[2][4], bf[4][2];
            #pragma unroll
            for (int i = 0; i < 2; i++) {
                const int r0 = wr + i * 16 + g;
                af[i][0] = Qs[r0][k0 + tig];
                af[i][1] = Qs[r0 + 8][k0 + tig];
                af[i][2] = Qs[r0][k0 + tig + 4];
                af[i][3] = Qs[r0 + 8][k0 + tig + 4];
            }
            #pragma unroll
            for (int j = 0; j < 4; j++) {
                const int c0 = wnq + j * 8 + g;
                bf[j][0] = Ts[ts][c0][k0 + tig];
                bf[j][1] = Ts[ts][c0][k0 + tig + 4];
            }
            #pragma unroll
            for (int i = 0; i < 2; i++)
                #pragma unroll
                for (int j = 0; j < 4; j++)
                    mma8(acc[i][j], af[i], bf[j]);
        }

        #pragma unroll
        for (int i = 0; i < 2; i++) {
            const int r0 = bm + wr + i * 16 + g;
            #pragma unroll
            for (int j = 0; j < 4; j++) {
                const int c0 = ck * 128 + wnq + j * 8 + tig * 2;
                int2 m0 = *(const int2*)(mbase + (size_t)r0 * S_ + c0);
                int2 m1 = *(const int2*)(mbase + (size_t)(r0 + 8) * S_ + c0);
                float e0 = m0.x ? __expf(acc[i][j][0] * 0.125f) : 0.f;
                float e1 = m0.y ? __expf(acc[i][j][1] * 0.125f) : 0.f;
                float e2 = m1.x ? __expf(acc[i][j][2] * 0.125f) : 0.f;
                float e3 = m1.y ? __expf(acc[i][j][3] * 0.125f) : 0.f;
                psum0[i] += e0 + e1;
                psum1[i] += e2 + e3;
            }
        }
        cp_wait<0>();
        __syncthreads();
    }

    #pragma unroll
    for (int i = 0; i < 2; i++) {
        psum0[i] += __shfl_xor_sync(~0u, psum0[i], 1);
        psum0[i] += __shfl_xor_sync(~0u, psum0[i], 2);
        psum1[i] += __shfl_xor_sync(~0u, psum1[i], 1);
        psum1[i] += __shfl_xor_sync(~0u, psum1[i], 2);
    }
    if (tig == 0) {
        #pragma unroll
        for (int i = 0; i < 2; i++) {
            rs[wc * 128 + wr + i * 16 + g]     = psum0[i];
            rs[wc * 128 + wr + i * 16 + g + 8] = psum1[i];
        }
    }
    issueT(0, 0);     // prefetch chunk 0 for sweep 2
    __syncthreads();
    if (tid < 128)
        rinv[tid] = 1.0f / (rs[tid] + rs[128 + tid] + rs[256 + tid] + rs[384 + tid]);
    cp_wait<0>();
    __syncthreads();

    // ---------------- sweep 2: weights out + PV ----------------
    float pv[2][2][4] = {};
    for (int ck = 0; ck < 8; ck++) {
        const int ts = ck & 1;
        if (ck + 1 < 8) issueT(ts ^ 1, ck + 1);

        float acc[2][4][4] = {};
        #pragma unroll
        for (int k0 = 0; k0 < 64; k0 += 8) {
            float af[2][4], bf[4][2];
            #pragma unroll
            for (int i = 0; i < 2; i++) {
                const int r0 = wr + i * 16 + g;
                af[i][0] = Qs[r0][k0 + tig];
                af[i][1] = Qs[r0 + 8][k0 + tig];
                af[i][2] = Qs[r0][k0 + tig + 4];
                af[i][3] = Qs[r0 + 8][k0 + tig + 4];
            }
            #pragma unroll
            for (int j = 0; j < 4; j++) {
                const int c0 = wnq + j * 8 + g;
                bf[j][0] = Ts[ts][c0][k0 + tig];
                bf[j][1] = Ts[ts][c0][k0 + tig + 4];
            }
            #pragma unroll
            for (int i = 0; i < 2; i++)
                #pragma unroll
                for (int j = 0; j < 4; j++)
                    mma8(acc[i][j], af[i], bf[j]);
        }

        #pragma unroll
        for (int i = 0; i < 2; i++) {
            const int lr0 = wr + i * 16 + g;
            const int r0 = bm + lr0;
            const float v0 = rinv[lr0], v1 = rinv[lr0 + 8];
            #pragma unroll
            for (int j = 0; j < 4; j++) {
                const int lc = wnq + j * 8 + tig * 2;
                const int c0 = ck * 128 + lc;
                int2 m0 = *(const int2*)(mbase + (size_t)r0 * S_ + c0);
                int2 m1 = *(const int2*)(mbase + (size_t)(r0 + 8) * S_ + c0);
                float e0 = m0.x ? __expf(acc[i][j][0] * 0.125f) * v0 : 0.f;
                float e1 = m0.y ? __expf(acc[i][j][1] * 0.125f) * v0 : 0.f;
                float e2 = m1.x ? __expf(acc[i][j][2] * 0.125f) * v1 : 0.f;
                float e3 = m1.y ? __expf(acc[i][j][3] * 0.125f) * v1 : 0.f;
                *(float2*)&Ps[lr0][lc]     = make_float2(to_tf32(e0), to_tf32(e1));
                *(float2*)&Ps[lr0 + 8][lc] = make_float2(to_tf32(e2), to_tf32(e3));
            }
        }
        __syncthreads();

        // PV accumulate: pv += Ps(128x128) @ V(128x64)
        #pragma unroll
        for (int k0 = 0; k0 < 128; k0 += 8) {
            float af[2][4], bf[2][2];
            #pragma unroll
            for (int i = 0; i < 2; i++) {
                const int r0 = wr + i * 16 + g;
                af[i][0] = Ps[r0][k0 + tig];
                af[i][1] = Ps[r0 + 8][k0 + tig];
                af[i][2] = Ps[r0][k0 + tig + 4];
                af[i][3] = Ps[r0 + 8][k0 + tig + 4];
            }
            #pragma unroll
            for (int j = 0; j < 2; j++) {
                const int c0 = wnp + j * 8 + g;
                bf[j][0] = Ts[ts][k0 + tig][c0];
                bf[j][1] = Ts[ts][k0 + tig + 4][c0];
            }
            #pragma unroll
            for (int i = 0; i < 2; i++)
                #pragma unroll
                for (int j = 0; j < 2; j++)
                    mma8(pv[i][j], af[i], bf[j]);
        }

        // normalized weights -> gmem (coalesced via Ps)
        {
            const int c = lane * 4;
            #pragma unroll
            for (int rr = 0; rr < 8; rr++) {
                const int r = warp + rr * 16;
                float4 v = *(const float4*)&Ps[r][c];
                *(float4*)(attnw + ((size_t)z * S_ + bm + r) * S_ + ck * 128 + c) = v;
            }
        }
        cp_wait<0>();
        __syncthreads();
    }

    // epilogue: attn_out (pre-rounded tf32 for the Wo gemm)
    #pragma unroll
    for (int i = 0; i < 2; i++) {
        const size_t gr0 = (size_t)(b * S_ + bm + wr + i * 16 + g);
        #pragma unroll
        for (int j = 0; j < 2; j++) {
            const int col = h * HD_ + wnp + j * 8 + tig * 2;
            *(float2*)(aout + gr0 * D_ + col) =
                make_float2(to_tf32(pv[i][j][0]), to_tf32(pv[i][j][1]));
            *(float2*)(aout + (gr0 + 8) * D_ + col) =
                make_float2(to_tf32(pv[i][j][2]), to_tf32(pv[i][j][3]));
        }
    }
}

// ---------------------------------------------------------------------------
// Fused residual add + LayerNorm.
// ---------------------------------------------------------------------------
__global__ __launch_bounds__(256) void add_ln_kernel(
    const float* __restrict__ a, const float* __restrict__ bres,
    const float* __restrict__ g, const float* __restrict__ beta,
    float* __restrict__ out)
{
    const size_t r = blockIdx.x;
    const int tid = threadIdx.x;
    float4 va = ((const float4*)(a + r * D_))[tid];
    float4 vb = ((const float4*)(bres + r * D_))[tid];
    float4 v = make_float4(va.x + vb.x, va.y + vb.y, va.z + vb.z, va.w + vb.w);

    float s = v.x + v.y + v.z + v.w;
    float sq = v.x * v.x + v.y * v.y + v.z * v.z + v.w * v.w;

    __shared__ float s1[8], s2[8];
    const int w = tid >> 5, l = tid & 31;
    #pragma unroll
    for (int o = 16; o; o >>= 1) {
        s  += __shfl_xor_sync(~0u, s, o);
        sq += __shfl_xor_sync(~0u, sq, o);
    }
    if (l == 0) { s1[w] = s; s2[w] = sq; }
    __syncthreads();
    s  = (s1[0] + s1[1]) + (s1[2] + s1[3]) + (s1[4] + s1[5]) + (s1[6] + s1[7]);
    sq = (s2[0] + s2[1]) + (s2[2] + s2[3]) + (s2[4] + s2[5]) + (s2[6] + s2[7]);

    const float mean = s * (1.0f / D_);
    const float var = sq * (1.0f / D_) - mean * mean;
    const float rstd = rsqrtf(var + 1e-12f);

    float4 gg = ((const float4*)g)[tid];
    float4 bb = ((const float4*)beta)[tid];
    float4 o;
    o.x = gg.x * (v.x - mean) * rstd + bb.x;
    o.y = gg.y * (v.y - mean) * rstd + bb.y;
    o.z = gg.z * (v.z - mean) * rstd + bb.z;
    o.w = gg.w * (v.w - mean) * rstd + bb.w;
    ((float4*)(out + r * D_))[tid] = o;
}

// ---------------------------------------------------------------------------
extern "C" void kernel_launch(void* const* d_in, const int* in_sizes, int n_in,
                              void* d_out, int out_size)
{
    const float* x    = (const float*)d_in[0];
    const int*   mask = (const int*)  d_in[1];
    const float* Wq   = (const float*)d_in[2];
    const float* bq   = (const float*)d_in[3];
    const float* Wo   = (const float*)d_in[4];
    const float* bo   = (const float*)d_in[5];
    const float* W1   = (const float*)d_in[6];
    const float* b1   = (const float*)d_in[7];
    const float* W2   = (const float*)d_in[8];
    const float* b2   = (const float*)d_in[9];
    const float* g1   = (const float*)d_in[10];
    const float* be1  = (const float*)d_in[11];
    const float* g2   = (const float*)d_in[12];
    const float* be2  = (const float*)d_in[13];

    float* out2 = (float*)d_out;
    float* attn = out2 + (size_t)ROWS_ * D_;

    float *q, *attn_out, *proj, *out1, *ff1, *wt;
    cudaGetSymbolAddress((void**)&q,        g_q);
    cudaGetSymbolAddress((void**)&attn_out, g_attn_out);
    cudaGetSymbolAddress((void**)&proj,     g_proj);
    cudaGetSymbolAddress((void**)&out1,     g_out1);
    cudaGetSymbolAddress((void**)&ff1,      g_ff1);
    cudaGetSymbolAddress((void**)&wt,       g_wt);

    float* Wq_t = wt;
    float* Wo_t = wt + 1024 * 1024;
    float* W1_t = wt + 2 * 1024 * 1024;
    float* W2_t = wt + 6 * 1024 * 1024;
    float* x_t  = ff1;   // ff1 region unused until step 5

    cudaFuncSetAttribute((const void*)k_gemm<0,0,1>,
        cudaFuncAttributeMaxDynamicSharedMemorySize, GEMM_SMEM);
    cudaFuncSetAttribute((const void*)k_gemm<0,0,0>,
        cudaFuncAttributeMaxDynamicSharedMemorySize, GEMM_SMEM);
    cudaFuncSetAttribute((const void*)k_gemm<1,1,1>,
        cudaFuncAttributeMaxDynamicSharedMemorySize, GEMM_SMEM);
    cudaFuncSetAttribute((const void*)k_attn,
        cudaFuncAttributeMaxDynamicSharedMemorySize, ATTN_SMEM);

    dim3 blk(256);

    // 0) pre-round inputs to tf32
    k_cvt<<<(ROWS_*D_/4 + 255)/256, blk>>>(x,  x_t,  ROWS_*D_/4);
    k_cvt<<<(D_*D_/4    + 255)/256, blk>>>(Wq, Wq_t, D_*D_/4);
    k_cvt<<<(D_*D_/4    + 255)/256, blk>>>(Wo, Wo_t, D_*D_/4);
    k_cvt<<<(D_*DFF_/4  + 255)/256, blk>>>(W1, W1_t, D_*DFF_/4);
    k_cvt<<<(D_*DFF_/4  + 255)/256, blk>>>(W2, W2_t, D_*DFF_/4);

    // 1) q = x @ Wq + bq  (output rounded)
    k_gemm<0,0,1><<<dim3(D_/128, ROWS_/128), blk, GEMM_SMEM>>>(
        x_t, D_, Wq_t, D_, q, D_, D_, bq);

    // 2) fused attention
    k_attn<<<dim3(S_/128, BH_), 512, ATTN_SMEM>>>(q, mask, attn, attn_out);

    // 3) proj = attn_out @ Wo + bo (exact output)
    k_gemm<0,0,0><<<dim3(D_/128, ROWS_/128), blk, GEMM_SMEM>>>(
        attn_out, D_, Wo_t, D_, proj, D_, D_, bo);

    // 4) out1 = LN(x + proj)   [original x]
    add_ln_kernel<<<ROWS_, blk>>>(x, proj, g1, be1, out1);

    // 5) ff1 = relu(out1 @ W1 + b1)  (A cvt at consume, output rounded)
    k_gemm<1,1,1><<<dim3(DFF_/128, ROWS_/128), blk, GEMM_SMEM>>>(
        out1, D_, W1_t, DFF_, ff1, DFF_, D_, b1);

    // 6) ff2 = ff1 @ W2 + b2 (exact output)
    k_gemm<0,0,0><<<dim3(D_/128, ROWS_/128), blk, GEMM_SMEM>>>(
        ff1, DFF_, W2_t, D_, proj, D_, DFF_, b2);

    // 7) out2 = LN(out1 + ff2)
    add_ln_kernel<<<ROWS_, blk>>>(out1, proj, g2, be2, out2);
}

// round 5
// speedup vs baseline: 3.1286x; 1.1035x over previous
#include <cuda_runtime.h>
#include <cstdint>
#include <cstddef>

// ---------------------------------------------------------------------------
// EncoderLayer B=4,S=1024,D=1024,H=16,HD=64,DFF=4096 fp32.
// TF32 mma GEMMs, ldmatrix fragment loads, transposed pre-rounded weights,
// cp.async pipelines, fused attention. q==k==v.
// ---------------------------------------------------------------------------

#define B_  4
#define S_  1024
#define D_  1024
#define H_  16
#define HD_ 64
#define DFF_ 4096
#define ROWS_ (B_*S_)
#define BH_ (B_*H_)

__device__ float g_q[ROWS_ * D_];
__device__ float g_attn_out[ROWS_ * D_];   // also reused as rounded out1
__device__ float g_proj[ROWS_ * D_];
__device__ float g_out1[ROWS_ * D_];
__device__ float g_ff1[(size_t)ROWS_ * DFF_];
__device__ float g_wt[10 * 1024 * 1024];   // Wq_t Wo_t W1_t W2_t (transposed)

__device__ __forceinline__ float to_tf32(float x) {
    unsigned u; asm("cvt.rna.tf32.f32 %0, %1;" : "=r"(u) : "f"(x));
    return __uint_as_float(u);
}
__device__ __forceinline__ void mma8u(float c[4],
    unsigned a0, unsigned a1, unsigned a2, unsigned a3,
    unsigned b0, unsigned b1) {
    asm volatile(
        "mma.sync.aligned.m16n8k8.row.col.f32.tf32.tf32.f32 "
        "{%0,%1,%2,%3}, {%4,%5,%6,%7}, {%8,%9}, {%0,%1,%2,%3};\n"
        : "+f"(c[0]), "+f"(c[1]), "+f"(c[2]), "+f"(c[3])
        : "r"(a0), "r"(a1), "r"(a2), "r"(a3), "r"(b0), "r"(b1));
}
__device__ __forceinline__ void ldsm4(unsigned addr, unsigned r[4]) {
    asm volatile("ldmatrix.sync.aligned.m8n8.x4.shared.b16 {%0,%1,%2,%3}, [%4];"
        : "=r"(r[0]), "=r"(r[1]), "=r"(r[2]), "=r"(r[3]) : "r"(addr));
}
__device__ __forceinline__ unsigned smem_u32(const void* p) {
    return (unsigned)__cvta_generic_to_shared(p);
}
__device__ __forceinline__ void cpa16(unsigned dst, const float* src) {
    asm volatile("cp.async.cg.shared.global [%0], [%1], 16;" :: "r"(dst), "l"(src));
}
__device__ __forceinline__ void cp_commit() {
    asm volatile("cp.async.commit_group;");
}
template<int N> __device__ __forceinline__ void cp_wait() {
    asm volatile("cp.async.wait_group %0;" :: "n"(N));
}

// ---------------------------------------------------------------------------
// tf32 pre-round (identity layout)
// ---------------------------------------------------------------------------
__global__ __launch_bounds__(256) void k_cvt(
    const float* __restrict__ src, float* __restrict__ dst, int n4)
{
    int i = blockIdx.x * 256 + threadIdx.x;
    if (i < n4) {
        float4 v = ((const float4*)src)[i];
        ((float4*)dst)[i] = make_float4(
            to_tf32(v.x), to_tf32(v.y), to_tf32(v.z), to_tf32(v.w));
    }
}

// tf32 pre-round + transpose: src[K][N] -> dst[N][K]
__global__ __launch_bounds__(256) void k_cvt_t(
    const float* __restrict__ src, float* __restrict__ dst, int K, int N)
{
    __shared__ float t[32][33];
    const int tx = threadIdx.x & 31, ty = threadIdx.x >> 5;
    const int k0 = blockIdx.y * 32, n0 = blockIdx.x * 32;
    #pragma unroll
    for (int i = 0; i < 4; i++)
        t[ty + i * 8][tx] = src[(size_t)(k0 + ty + i * 8) * N + n0 + tx];
    __syncthreads();
    #pragma unroll
    for (int i = 0; i < 4; i++)
        dst[(size_t)(n0 + ty + i * 8) * K + k0 + tx] = to_tf32(t[tx][ty + i * 8]);
}

// ---------------------------------------------------------------------------
// Pipelined GEMM, both operands k-major: C[M,N] = A[M,K] @ Bt[N,K]^T + bias.
// BM=BN=128, BK=16, 256 thr, 3-stage cp.async, ldmatrix fragments.
// ---------------------------------------------------------------------------
#define GEMM_SMEM (3 * 2 * (128 * 20) * 4)

template<int RELU, int ROUND_C>
__global__ __launch_bounds__(256, 2) void k_gemm(
    const float* __restrict__ A, int lda,
    const float* __restrict__ Bt, int ldb,
    float* __restrict__ C, int ldc,
    int K, const float* __restrict__ bias)
{
    constexpr int ST = 3;
    extern __shared__ float sm[];
    float (*As)[128][20] = reinterpret_cast<float(*)[128][20]>(sm);
    float (*Bs)[128][20] = reinterpret_cast<float(*)[128][20]>(sm + ST * 128 * 20);

    const int tid = threadIdx.x, lane = tid & 31, warp = tid >> 5;
    const int wm = (warp >> 2) * 64, wn = (warp & 3) * 32;
    const int g = lane >> 2, tig = lane & 3;
    const int bm = blockIdx.y * 128, bn = blockIdx.x * 128;

    const int ar = tid >> 2, akq = (tid & 3) * 4;

    const float* Ag  = A  + (size_t)(bm + ar) * lda + akq;
    const float* Ag2 = Ag + (size_t)64 * lda;
    const float* Bg  = Bt + (size_t)(bn + ar) * ldb + akq;
    const float* Bg2 = Bg + (size_t)64 * ldb;

    auto issue = [&](int s, int kk) {
        cpa16(smem_u32(&As[s][ar][akq]),      Ag + kk);
        cpa16(smem_u32(&As[s][ar + 64][akq]), Ag2 + kk);
        cpa16(smem_u32(&Bs[s][ar][akq]),      Bg + kk);
        cpa16(smem_u32(&Bs[s][ar + 64][akq]), Bg2 + kk);
        cp_commit();
    };

    // ldmatrix lane offsets (bytes)
    const unsigned aoff = ((lane & 15) * 20 + (lane >> 4) * 4) * 4;
    const unsigned boff = ((((lane >> 4) & 1) * 8 + (lane & 7)) * 20
                           + ((lane >> 3) & 1) * 4) * 4;

    float acc[4][4][4] = {};
    const int nk = K / 16;
    issue(0, 0);
    issue(1, 16);

    for (int t = 0; t < nk; t++) {
        cp_wait<ST - 2>();
        __syncthreads();
        if (t + 2 < nk) issue((t + 2) % ST, (t + 2) * 16);
        const int s = t % ST;
        const unsigned aBase = smem_u32(&As[s][wm][0]) + aoff;
        const unsigned bBase = smem_u32(&Bs[s][wn][0]) + boff;
        #pragma unroll
        for (int k0 = 0; k0 < 16; k0 += 8) {
            unsigned af[4][4], bb[2][4];
            #pragma unroll
            for (int i = 0; i < 4; i++)
                ldsm4(aBase + i * (16 * 80) + k0 * 4, af[i]);
            #pragma unroll
            for (int jj = 0; jj < 2; jj++)
                ldsm4(bBase + jj * (16 * 80) + k0 * 4, bb[jj]);
            #pragma unroll
            for (int i = 0; i < 4; i++)
                #pragma unroll
                for (int j = 0; j < 4; j++)
                    mma8u(acc[i][j], af[i][0], af[i][1], af[i][2], af[i][3],
                          bb[j >> 1][(j & 1) * 2], bb[j >> 1][(j & 1) * 2 + 1]);
        }
        __syncthreads();
    }

    #pragma unroll
    for (int i = 0; i < 4; i++) {
        #pragma unroll
        for (int j = 0; j < 4; j++) {
            const int col = bn + wn + j * 8 + tig * 2;
            float2 bbv = *(const float2*)(bias + col);
            float2 v0 = make_float2(acc[i][j][0] + bbv.x, acc[i][j][1] + bbv.y);
            float2 v1 = make_float2(acc[i][j][2] + bbv.x, acc[i][j][3] + bbv.y);
            if (RELU) {
                v0.x = fmaxf(v0.x, 0.f); v0.y = fmaxf(v0.y, 0.f);
                v1.x = fmaxf(v1.x, 0.f); v1.y = fmaxf(v1.y, 0.f);
            }
            if (ROUND_C) {
                v0.x = to_tf32(v0.x); v0.y = to_tf32(v0.y);
                v1.x = to_tf32(v1.x); v1.y = to_tf32(v1.y);
            }
            const int r0 = bm + wm + i * 16 + g;
            *(float2*)(C + (size_t)r0 * ldc + col) = v0;
            *(float2*)(C + (size_t)(r0 + 8) * ldc + col) = v1;
        }
    }
}

// ---------------------------------------------------------------------------
// Fused attention, 512 threads, ldmatrix fragments.
// ---------------------------------------------------------------------------
#define Q_STR  68
#define T_STR  68
#define P_STR  132
#define ATTN_SMEM ((128*Q_STR + 2*128*T_STR + 128*P_STR + 4*128 + 128) * 4)

__global__ __launch_bounds__(512, 1) void k_attn(
    const float* __restrict__ qbuf, const int* __restrict__ mask,
    float* __restrict__ attnw, float* __restrict__ aout)
{
    extern __shared__ float sm[];
    float (*Qs)[Q_STR] = reinterpret_cast<float(*)[Q_STR]>(sm);
    float (*Ts)[128][T_STR] =
        reinterpret_cast<float(*)[128][T_STR]>(sm + 128 * Q_STR);
    float (*Ps)[P_STR] =
        reinterpret_cast<float(*)[P_STR]>(sm + 128 * Q_STR + 2 * 128 * T_STR);
    float* rs   = sm + 128 * Q_STR + 2 * 128 * T_STR + 128 * P_STR;
    float* rinv = rs + 4 * 128;

    const int tid = threadIdx.x, lane = tid & 31, warp = tid >> 5;
    const int g = lane >> 2, tig = lane & 3;
    const int wr = (warp >> 2) * 32;
    const int wc = warp & 3;
    const int wnq = wc * 32;
    const int wnp = wc * 16;
    const int qb = blockIdx.x, z = blockIdx.y;
    const int b = z >> 4, h = z & 15;
    const float* hs = qbuf + (size_t)b * S_ * D_ + h * HD_;
    const int bm = qb * 128;

    const unsigned aoffQ = ((lane & 15) * Q_STR + (lane >> 4) * 4) * 4;
    const unsigned aoffP = ((lane & 15) * P_STR + (lane >> 4) * 4) * 4;
    const unsigned boffT = ((((lane >> 4) & 1) * 8 + (lane & 7)) * T_STR
                            + ((lane >> 3) & 1) * 4) * 4;

    const int lr = tid >> 2, lcb = (tid & 3) * 16;

    {
        const float* src = hs + (size_t)(bm + lr) * D_ + lcb;
        #pragma unroll
        for (int i = 0; i < 4; i++)
            cpa16(smem_u32(&Qs[lr][lcb + i * 4]), src + i * 4);
        cp_commit();
    }
    auto issueT = [&](int buf, int ck) {
        const float* src = hs + (size_t)(ck * 128 + lr) * D_ + lcb;
        #pragma unroll
        for (int i = 0; i < 4; i++)
            cpa16(smem_u32(&Ts[buf][lr][lcb + i * 4]), src + i * 4);
        cp_commit();
    };
    issueT(0, 0);
    cp_wait<0>();
    __syncthreads();

    const int* mbase = mask + (size_t)b * S_ * S_;
    const unsigned qBase = smem_u32(&Qs[wr][0]) + aoffQ;

    // ---------------- sweep 1: row sums of masked exp ----------------
    float psum0[2] = {}, psum1[2] = {};
    for (int ck = 0; ck < 8; ck++) {
        const int ts = ck & 1;
        if (ck + 1 < 8) issueT(ts ^ 1, ck + 1);
        const unsigned tBase = smem_u32(&Ts[ts][wnq][0]) + boffT;

        float acc[2][4][4] = {};
        #pragma unroll
        for (int k0 = 0; k0 < 64; k0 += 8) {
            unsigned af[2][4], bb[2][4];
            #pragma unroll
            for (int i = 0; i < 2; i++)
                ldsm4(qBase + i * (16 * Q_STR * 4) + k0 * 4, af[i]);
            #pragma unroll
            for (int jj = 0; jj < 2; jj++)
                ldsm4(tBase + jj * (16 * T_STR * 4) + k0 * 4, bb[jj]);
            #pragma unroll
            for (int i = 0; i < 2; i++)
                #pragma unroll
                for (int j = 0; j < 4; j++)
                    mma8u(acc[i][j], af[i][0], af[i][1], af[i][2], af[i][3],
                          bb[j >> 1][(j & 1) * 2], bb[j >> 1][(j & 1) * 2 + 1]);
        }

        #pragma unroll
        for (int i = 0; i < 2; i++) {
            const int r0 = bm + wr + i * 16 + g;
            #pragma unroll
            for (int j = 0; j < 4; j++) {
                const int c0 = ck * 128 + wnq + j * 8 + tig * 2;
                int2 m0 = *(const int2*)(mbase + (size_t)r0 * S_ + c0);
                int2 m1 = *(const int2*)(mbase + (size_t)(r0 + 8) * S_ + c0);
                float e0 = m0.x ? __expf(acc[i][j][0] * 0.125f) : 0.f;
                float e1 = m0.y ? __expf(acc[i][j][1] * 0.125f) : 0.f;
                float e2 = m1.x ? __expf(acc[i][j][2] * 0.125f) : 0.f;
                float e3 = m1.y ? __expf(acc[i][j][3] * 0.125f) : 0.f;
                psum0[i] += e0 + e1;
                psum1[i] += e2 + e3;
            }
        }
        cp_wait<0>();
        __syncthreads();
    }

    #pragma unroll
    for (int i = 0; i < 2; i++) {
        psum0[i] += __shfl_xor_sync(~0u, psum0[i], 1);
        psum0[i] += __shfl_xor_sync(~0u, psum0[i], 2);
        psum1[i] += __shfl_xor_sync(~0u, psum1[i], 1);
        psum1[i] += __shfl_xor_sync(~0u, psum1[i], 2);
    }
    if (tig == 0) {
        #pragma unroll
        for (int i = 0; i < 2; i++) {
            rs[wc * 128 + wr + i * 16 + g]     = psum0[i];
            rs[wc * 128 + wr + i * 16 + g + 8] = psum1[i];
        }
    }
    issueT(0, 0);
    __syncthreads();
    if (tid < 128)
        rinv[tid] = 1.0f / (rs[tid] + rs[128 + tid] + rs[256 + tid] + rs[384 + tid]);
    cp_wait<0>();
    __syncthreads();

    // ---------------- sweep 2: weights out + PV ----------------
    float pv[2][2][4] = {};
    const unsigned pBase = smem_u32(&Ps[wr][0]) + aoffP;

    for (int ck = 0; ck < 8; ck++) {
        const int ts = ck & 1;
        if (ck + 1 < 8) issueT(ts ^ 1, ck + 1);
        const unsigned tBase = smem_u32(&Ts[ts][wnq][0]) + boffT;

        float acc[2][4][4] = {};
        #pragma unroll
        for (int k0 = 0; k0 < 64; k0 += 8) {
            unsigned af[2][4], bb[2][4];
            #pragma unroll
            for (int i = 0; i < 2; i++)
                ldsm4(qBase + i * (16 * Q_STR * 4) + k0 * 4, af[i]);
            #pragma unroll
            for (int jj = 0; jj < 2; jj++)
                ldsm4(tBase + jj * (16 * T_STR * 4) + k0 * 4, bb[jj]);
            #pragma unroll
            for (int i = 0; i < 2; i++)
                #pragma unroll
                for (int j = 0; j < 4; j++)
                    mma8u(acc[i][j], af[i][0], af[i][1], af[i][2], af[i][3],
                          bb[j >> 1][(j & 1) * 2], bb[j >> 1][(j & 1) * 2 + 1]);
        }

        #pragma unroll
        for (int i = 0; i < 2; i++) {
            const int lr0 = wr + i * 16 + g;
            const int r0 = bm + lr0;
            const float v0 = rinv[lr0], v1 = rinv[lr0 + 8];
            #pragma unroll
            for (int j = 0; j < 4; j++) {
                const int lc = wnq + j * 8 + tig * 2;
                const int c0 = ck * 128 + lc;
                int2 m0 = *(const int2*)(mbase + (size_t)r0 * S_ + c0);
                int2 m1 = *(const int2*)(mbase + (size_t)(r0 + 8) * S_ + c0);
                float e0 = m0.x ? __expf(acc[i][j][0] * 0.125f) * v0 : 0.f;
                float e1 = m0.y ? __expf(acc[i][j][1] * 0.125f) * v0 : 0.f;
                float e2 = m1.x ? __expf(acc[i][j][2] * 0.125f) * v1 : 0.f;
                float e3 = m1.y ? __expf(acc[i][j][3] * 0.125f) * v1 : 0.f;
                *(float2*)&Ps[lr0][lc]     = make_float2(to_tf32(e0), to_tf32(e1));
                *(float2*)&Ps[lr0 + 8][lc] = make_float2(to_tf32(e2), to_tf32(e3));
            }
        }
        __syncthreads();

        // PV accumulate: pv += Ps(128x128) @ V(128x64)
        #pragma unroll
        for (int k0 = 0; k0 < 128; k0 += 8) {
            unsigned af[2][4];
            float bf[2][2];
            #pragma unroll
            for (int i = 0; i < 2; i++)
                ldsm4(pBase + i * (16 * P_STR * 4) + k0 * 4, af[i]);
            #pragma unroll
            for (int j = 0; j < 2; j++) {
                const int c0 = wnp + j * 8 + g;
                bf[j][0] = Ts[ts][k0 + tig][c0];
                bf[j][1] = Ts[ts][k0 + tig + 4][c0];
            }
            #pragma unroll
            for (int i = 0; i < 2; i++)
                #pragma unroll
                for (int j = 0; j < 2; j++)
                    mma8u(pv[i][j], af[i][0], af[i][1], af[i][2], af[i][3],
                          __float_as_uint(bf[j][0]), __float_as_uint(bf[j][1]));
        }

        {
            const int c = lane * 4;
            #pragma unroll
            for (int rr = 0; rr < 8; rr++) {
                const int r = warp + rr * 16;
                float4 v = *(const float4*)&Ps[r][c];
                *(float4*)(attnw + ((size_t)z * S_ + bm + r) * S_ + ck * 128 + c) = v;
            }
        }
        cp_wait<0>();
        __syncthreads();
    }

    #pragma unroll
    for (int i = 0; i < 2; i++) {
        const size_t gr0 = (size_t)(b * S_ + bm + wr + i * 16 + g);
        #pragma unroll
        for (int j = 0; j < 2; j++) {
            const int col = h * HD_ + wnp + j * 8 + tig * 2;
            *(float2*)(aout + gr0 * D_ + col) =
                make_float2(to_tf32(pv[i][j][0]), to_tf32(pv[i][j][1]));
            *(float2*)(aout + (gr0 + 8) * D_ + col) =
                make_float2(to_tf32(pv[i][j][2]), to_tf32(pv[i][j][3]));
        }
    }
}

// ---------------------------------------------------------------------------
// Fused residual add + LayerNorm.
// ---------------------------------------------------------------------------
__global__ __launch_bounds__(256) void add_ln_kernel(
    const float* __restrict__ a, const float* __restrict__ bres,
    const float* __restrict__ g, const float* __restrict__ beta,
    float* __restrict__ out)
{
    const size_t r = blockIdx.x;
    const int tid = threadIdx.x;
    float4 va = ((const float4*)(a + r * D_))[tid];
    float4 vb = ((const float4*)(bres + r * D_))[tid];
    float4 v = make_float4(va.x + vb.x, va.y + vb.y, va.z + vb.z, va.w + vb.w);

    float s = v.x + v.y + v.z + v.w;
    float sq = v.x * v.x + v.y * v.y + v.z * v.z + v.w * v.w;

    __shared__ float s1[8], s2[8];
    const int w = tid >> 5, l = tid & 31;
    #pragma unroll
    for (int o = 16; o; o >>= 1) {
        s  += __shfl_xor_sync(~0u, s, o);
        sq += __shfl_xor_sync(~0u, sq, o);
    }
    if (l == 0) { s1[w] = s; s2[w] = sq; }
    __syncthreads();
    s  = (s1[0] + s1[1]) + (s1[2] + s1[3]) + (s1[4] + s1[5]) + (s1[6] + s1[7]);
    sq = (s2[0] + s2[1]) + (s2[2] + s2[3]) + (s2[4] + s2[5]) + (s2[6] + s2[7]);

    const float mean = s * (1.0f / D_);
    const float var = sq * (1.0f / D_) - mean * mean;
    const float rstd = rsqrtf(var + 1e-12f);

    float4 gg = ((const float4*)g)[tid];
    float4 bb = ((const float4*)beta)[tid];
    float4 o;
    o.x = gg.x * (v.x - mean) * rstd + bb.x;
    o.y = gg.y * (v.y - mean) * rstd + bb.y;
    o.z = gg.z * (v.z - mean) * rstd + bb.z;
    o.w = gg.w * (v.w - mean) * rstd + bb.w;
    ((float4*)(out + r * D_))[tid] = o;
}

// ---------------------------------------------------------------------------
extern "C" void kernel_launch(void* const* d_in, const int* in_sizes, int n_in,
                              void* d_out, int out_size)
{
    const float* x    = (const float*)d_in[0];
    const int*   mask = (const int*)  d_in[1];
    const float* Wq   = (const float*)d_in[2];
    const float* bq   = (const float*)d_in[3];
    const float* Wo   = (const float*)d_in[4];
    const float* bo   = (const float*)d_in[5];
    const float* W1   = (const float*)d_in[6];
    const float* b1   = (const float*)d_in[7];
    const float* W2   = (const float*)d_in[8];
    const float* b2   = (const float*)d_in[9];
    const float* g1   = (const float*)d_in[10];
    const float* be1  = (const float*)d_in[11];
    const float* g2   = (const float*)d_in[12];
    const float* be2  = (const float*)d_in[13];

    float* out2 = (float*)d_out;
    float* attn = out2 + (size_t)ROWS_ * D_;

    float *q, *attn_out, *proj, *out1, *ff1, *wt;
    cudaGetSymbolAddress((void**)&q,        g_q);
    cudaGetSymbolAddress((void**)&attn_out, g_attn_out);
    cudaGetSymbolAddress((void**)&proj,     g_proj);
    cudaGetSymbolAddress((void**)&out1,     g_out1);
    cudaGetSymbolAddress((void**)&ff1,      g_ff1);
    cudaGetSymbolAddress((void**)&wt,       g_wt);

    float* Wq_t = wt;                        // [D][D]   (n-major)
    float* Wo_t = wt + 1024 * 1024;          // [D][D]
    float* W1_t = wt + 2 * 1024 * 1024;      // [DFF][D]
    float* W2_t = wt + 6 * 1024 * 1024;      // [D][DFF]
    float* x_t  = ff1;                       // ff1 free until step 6

    cudaFuncSetAttribute((const void*)k_gemm<0,1>,
        cudaFuncAttributeMaxDynamicSharedMemorySize, GEMM_SMEM);
    cudaFuncSetAttribute((const void*)k_gemm<0,0>,
        cudaFuncAttributeMaxDynamicSharedMemorySize, GEMM_SMEM);
    cudaFuncSetAttribute((const void*)k_gemm<1,1>,
        cudaFuncAttributeMaxDynamicSharedMemorySize, GEMM_SMEM);
    cudaFuncSetAttribute((const void*)k_attn,
        cudaFuncAttributeMaxDynamicSharedMemorySize, ATTN_SMEM);

    dim3 blk(256);

    // 0) pre-round x; pre-round + transpose weights
    k_cvt<<<(ROWS_*D_/4 + 255)/256, blk>>>(x, x_t, ROWS_*D_/4);
    k_cvt_t<<<dim3(D_/32,   D_/32), blk>>>(Wq, Wq_t, D_,   D_);
    k_cvt_t<<<dim3(D_/32,   D_/32), blk>>>(Wo, Wo_t, D_,   D_);
    k_cvt_t<<<dim3(DFF_/32, D_/32), blk>>>(W1, W1_t, D_,   DFF_);
    k_cvt_t<<<dim3(D_/32, DFF_/32), blk>>>(W2, W2_t, DFF_, D_);

    // 1) q = x @ Wq + bq  (rounded output)
    k_gemm<0,1><<<dim3(D_/128, ROWS_/128), blk, GEMM_SMEM>>>(
        x_t, D_, Wq_t, D_, q, D_, D_, bq);

    // 2) fused attention
    k_attn<<<dim3(S_/128, BH_), 512, ATTN_SMEM>>>(q, mask, attn, attn_out);

    // 3) proj = attn_out @ Wo + bo (exact output)
    k_gemm<0,0><<<dim3(D_/128, ROWS_/128), blk, GEMM_SMEM>>>(
        attn_out, D_, Wo_t, D_, proj, D_, D_, bo);

    // 4) out1 = LN(x + proj)
    add_ln_kernel<<<ROWS_, blk>>>(x, proj, g1, be1, out1);

    // 5) round out1 for the FFN1 A operand (attn_out buffer is free now)
    k_cvt<<<(ROWS_*D_/4 + 255)/256, blk>>>(out1, attn_out, ROWS_*D_/4);

    // 6) ff1 = relu(out1 @ W1 + b1)  (rounded output)
    k_gemm<1,1><<<dim3(DFF_/128, ROWS_/128), blk, GEMM_SMEM>>>(
        attn_out, D_, W1_t, DFF_ ? D_ : D_, ff1, DFF_, D_, b1);

    // 7) ff2 = ff1 @ W2 + b2 (exact output)
    k_gemm<0,0><<<dim3(D_/128, ROWS_/128), blk, GEMM_SMEM>>>(
        ff1, DFF_, W2_t, DFF_, proj, D_, DFF_, b2);

    // 8) out2 = LN(out1 + ff2)
    add_ln_kernel<<<ROWS_, blk>>>(out1, proj, g2, be2, out2);
}